// round 7
// baseline (speedup 1.0000x reference)
#include <cuda_runtime.h>
#include <cstdint>

#define GROUPS  2048
#define MM      64
#define CC      128
#define TOK     8192
#define RK      8
#define RRR     512
#define MASKN   524288

__device__ float g_s  [(size_t)GROUPS * TOK];  // 64 MB group sums
__device__ float g_t1h[(size_t)GROUPS * RRR];  // 4 MB  T1 hi (tf32)
__device__ float g_t1l[(size_t)GROUPS * RRR];  // 4 MB  T1 lo (tf32)
__device__ float g_u2 [(size_t)GROUPS * RRR];  // 4 MB
__device__ float g_w4h[RRR * RRR];             // 1 MB  W4 hi
__device__ float g_w4l[RRR * RRR];             // 1 MB  W4 lo
__device__ int   g_flags[2];                   // [ge2, odd]

__device__ __forceinline__ void tf32_split(float v, float& hi, float& lo)
{
    unsigned hb, lb;
    asm("cvt.rna.tf32.f32 %0, %1;" : "=r"(hb) : "f"(v));
    hi = __uint_as_float(hb);
    float r = v - hi;
    asm("cvt.rna.tf32.f32 %0, %1;" : "=r"(lb) : "f"(r));
    lo = __uint_as_float(lb);
}

// ---------------------------------------------------------------------------
// Mask dtype scan
// ---------------------------------------------------------------------------
__global__ void __launch_bounds__(256) k0_scan_mask(const unsigned char* __restrict__ mask)
{
    const uint4* p = (const uint4*)mask;
    unsigned acc = 0;
    int i = blockIdx.x * 256 + threadIdx.x;
    for (; i < MASKN / 16; i += 64 * 256) {
        uint4 v = p[i];
        acc |= (v.x | v.y | v.z | v.w);
    }
    __shared__ unsigned sacc;
    if (threadIdx.x == 0) sacc = 0;
    __syncthreads();
    #pragma unroll
    for (int off = 16; off >= 1; off >>= 1)
        acc |= __shfl_xor_sync(0xffffffffu, acc, off);
    if ((threadIdx.x & 31) == 0) atomicOr(&sacc, acc);
    __syncthreads();
    if (threadIdx.x == 0) {
        unsigned a = sacc;
        if (a & 0xFEFEFEFEu) atomicOr(&g_flags[0], 1);
        if (a & 0xFFFFFF00u) atomicOr(&g_flags[1], 1);
    }
}

// ---------------------------------------------------------------------------
// Fold: W4[(o,p,C),(a,d,F)] -> hi/lo tf32 pair. 64 blocks.
// ---------------------------------------------------------------------------
__global__ void __launch_bounds__(256) fold_w4(
    const float* __restrict__ core,
    const float* __restrict__ of0, const float* __restrict__ of1,
    const float* __restrict__ if0, const float* __restrict__ if1)
{
    __shared__ float bufA[4096], bufB[4096];
    __shared__ float sf[4][64];
    const int tid = threadIdx.x;
    const int C = blockIdx.x >> 3, F = blockIdx.x & 7;

    if (tid < 64)       sf[0][tid]       = of0[tid];
    else if (tid < 128) sf[1][tid - 64]  = of1[tid - 64];
    else if (tid < 192) sf[2][tid - 128] = if0[tid - 128];
    else                sf[3][tid - 192] = if1[tid - 192];

    #pragma unroll
    for (int i = tid; i < 4096; i += 256) {
        int A = i >> 9, B = (i >> 6) & 7, D = (i >> 3) & 7, E = i & 7;
        bufA[i] = core[A * 32768 + B * 4096 + C * 512 + D * 64 + E * 8 + F];
    }
    __syncthreads();
    #pragma unroll
    for (int i = tid; i < 4096; i += 256) {   // M1[A,B,D,d] = sum_E K * if1[d,E]
        int ABD = i >> 3, d = i & 7;
        float acc = 0.f;
        #pragma unroll
        for (int E = 0; E < 8; E++) acc += bufA[ABD * 8 + E] * sf[3][d * 8 + E];
        bufB[i] = acc;
    }
    __syncthreads();
    #pragma unroll
    for (int i = tid; i < 4096; i += 256) {   // M2[A,B,d,a] = sum_D M1 * if0[a,D]
        int AB = i >> 6, d = (i >> 3) & 7, a = i & 7;
        float acc = 0.f;
        #pragma unroll
        for (int D = 0; D < 8; D++) acc += bufB[(AB * 8 + D) * 8 + d] * sf[2][a * 8 + D];
        bufA[i] = acc;
    }
    __syncthreads();
    #pragma unroll
    for (int i = tid; i < 4096; i += 256) {   // M3[B,d,a,o] = sum_A M2 * of0[o,A]
        int B = i >> 9, d = (i >> 6) & 7, a = (i >> 3) & 7, o = i & 7;
        float acc = 0.f;
        #pragma unroll
        for (int A = 0; A < 8; A++)
            acc += bufA[((A * 8 + B) * 8 + d) * 8 + a] * sf[0][o * 8 + A];
        bufB[i] = acc;
    }
    __syncthreads();
    #pragma unroll
    for (int i = tid; i < 4096; i += 256) {   // W4 = sum_B M3 * of1[p,B]
        int o = i >> 9, p = (i >> 6) & 7, a = (i >> 3) & 7, d = i & 7;
        float acc = 0.f;
        #pragma unroll
        for (int B = 0; B < 8; B++)
            acc += bufB[((B * 8 + d) * 8 + a) * 8 + o] * sf[1][p * 8 + B];
        float hi, lo;
        tf32_split(acc, hi, lo);
        size_t idx = (size_t)((o * 8 + p) * 8 + C) * RRR + a * 64 + d * 8 + F;
        g_w4h[idx] = hi;
        g_w4l[idx] = lo;
    }
}

// ---------------------------------------------------------------------------
// Kernel 1: grid 4096 (half-group per block): s -> scratch, T1 hi/lo.
// ---------------------------------------------------------------------------
__global__ void __launch_bounds__(256) k1_reduce_project(
    const float* __restrict__ x,
    const float* __restrict__ in_f2)   // (128,8)
{
    __shared__ float s[32 * 129];
    __shared__ float f2s[CC * RK];

    const int tid = threadIdx.x;
    const int g = blockIdx.x >> 1, h = blockIdx.x & 1;
    const size_t base = (size_t)g * (4 * TOK) + h * 4096;

    #pragma unroll
    for (int i = tid; i < CC * RK; i += 256) f2s[i] = in_f2[i];

    const float4* xb = (const float4*)(x + base);
    float4*       sg = (float4*)(g_s + (size_t)g * TOK + h * 4096);
    #pragma unroll
    for (int it = 0; it < 4; it++) {
        int i = tid + it * 256;
        float4 v0 = xb[i];
        float4 v1 = xb[i + 2048];
        float4 v2 = xb[i + 4096];
        float4 v3 = xb[i + 6144];
        float4 r;
        r.x = (v0.x + v1.x) + (v2.x + v3.x);
        r.y = (v0.y + v1.y) + (v2.y + v3.y);
        r.z = (v0.z + v1.z) + (v2.z + v3.z);
        r.w = (v0.w + v1.w) + (v2.w + v3.w);
        sg[i] = r;
        int m = i >> 5;
        int e = (i & 31) << 2;
        float* sp = &s[m * 129 + e];
        sp[0] = r.x; sp[1] = r.y; sp[2] = r.z; sp[3] = r.w;
    }
    __syncthreads();
    {
        int m = tid & 31;
        int F = tid >> 5;
        float acc = 0.f;
        const float* srow = &s[m * 129];
        #pragma unroll 8
        for (int e = 0; e < CC; e++)
            acc += srow[e] * f2s[e * RK + F];
        float hi, lo;
        tf32_split(acc, hi, lo);
        size_t idx = (size_t)g * RRR + (h * 32 + m) * 8 + F;
        g_t1h[idx] = hi;
        g_t1l[idx] = lo;
    }
}

// ---------------------------------------------------------------------------
// Kernel 2: U2 = T1 @ W4^T via mma.sync.m16n8k8.tf32, 3xTF32 split.
// Block 128x64, BK=32, 256 thr, warps 4(m)x2(n), warp tile 32x32.
// grid = (16, 8) = 128 blocks. DYNAMIC smem (49,664 B > 48 KB static limit).
// ---------------------------------------------------------------------------
#define ASS 1032
#define BSS 520
extern __shared__ float k2_smem[];
__global__ void __launch_bounds__(256) k2_core_gemm()
{
    float* Ah = k2_smem;                 // 4*ASS
    float* Al = Ah + 4 * ASS;            // 4*ASS
    float* Bh = Al + 4 * ASS;            // 4*BSS
    float* Bl = Bh + 4 * BSS;            // 4*BSS

    const int tid  = threadIdx.x;
    const int lane = tid & 31;
    const int wid  = tid >> 5;
    const int wm   = wid >> 1;          // 0..3 -> m offset wm*32
    const int wn   = wid & 1;           // 0..1 -> n offset wn*32
    const int gid  = lane >> 2;
    const int tig  = lane & 3;
    const int bm   = blockIdx.x * 128;
    const int bn   = blockIdx.y * 64;

    float acc[2][4][4];
    #pragma unroll
    for (int mi = 0; mi < 2; mi++)
        #pragma unroll
        for (int ni = 0; ni < 4; ni++)
            #pragma unroll
            for (int r = 0; r < 4; r++) acc[mi][ni][r] = 0.f;

    for (int k0 = 0; k0 < RRR; k0 += 32) {
        __syncthreads();
        // ---- stage A (hi & lo): 128 rows x 32 cols ----
        #pragma unroll
        for (int l = 0; l < 4; l++) {
            int fidx = tid + l * 256;              // float4 units, 1024 total
            int row = fidx >> 3;
            int c4  = (fidx & 7) << 2;
            int mt = row >> 4, tr = row & 15;
            int ks = c4 >> 3;
            int reg = (tr >> 3) + (((c4 & 7) >> 2) << 1);
            int basea = ks * ASS + mt * 128 + (tr & 7) * 16 + reg;
            float4 vh = *(const float4*)(g_t1h + (size_t)(bm + row) * RRR + k0 + c4);
            float4 vl = *(const float4*)(g_t1l + (size_t)(bm + row) * RRR + k0 + c4);
            Ah[basea]      = vh.x; Ah[basea + 4]  = vh.y;
            Ah[basea + 8]  = vh.z; Ah[basea + 12] = vh.w;
            Al[basea]      = vl.x; Al[basea + 4]  = vl.y;
            Al[basea + 8]  = vl.z; Al[basea + 12] = vl.w;
        }
        // ---- stage B (hi & lo): 64 rows x 32 cols ----
        #pragma unroll
        for (int l = 0; l < 2; l++) {
            int fidx = tid + l * 256;              // 512 total
            int n  = fidx >> 3;
            int c4 = (fidx & 7) << 2;
            int nt = n >> 3, tn = n & 7;
            int ks = c4 >> 3;
            int reg = (c4 >> 2) & 1;
            int baseb = ks * BSS + nt * 64 + tn * 8 + reg;
            float4 vh = *(const float4*)(g_w4h + (size_t)(bn + n) * RRR + k0 + c4);
            float4 vl = *(const float4*)(g_w4l + (size_t)(bn + n) * RRR + k0 + c4);
            Bh[baseb]     = vh.x; Bh[baseb + 2] = vh.y;
            Bh[baseb + 4] = vh.z; Bh[baseb + 6] = vh.w;
            Bl[baseb]     = vl.x; Bl[baseb + 2] = vl.y;
            Bl[baseb + 4] = vl.z; Bl[baseb + 6] = vl.w;
        }
        __syncthreads();

        #pragma unroll
        for (int ks = 0; ks < 4; ks++) {
            uint4 ah[2], al[2];
            uint2 bh[4], bl[4];
            #pragma unroll
            for (int mi = 0; mi < 2; mi++) {
                int mt = wm * 2 + mi;
                ah[mi] = *(const uint4*)&Ah[ks * ASS + mt * 128 + lane * 4];
                al[mi] = *(const uint4*)&Al[ks * ASS + mt * 128 + lane * 4];
            }
            #pragma unroll
            for (int ni = 0; ni < 4; ni++) {
                int nt = wn * 4 + ni;
                bh[ni] = *(const uint2*)&Bh[ks * BSS + nt * 64 + lane * 2];
                bl[ni] = *(const uint2*)&Bl[ks * BSS + nt * 64 + lane * 2];
            }
            #pragma unroll
            for (int mi = 0; mi < 2; mi++)
                #pragma unroll
                for (int ni = 0; ni < 4; ni++) {
                    float* c = acc[mi][ni];
                    asm volatile(
                        "mma.sync.aligned.m16n8k8.row.col.f32.tf32.tf32.f32 "
                        "{%0,%1,%2,%3}, {%4,%5,%6,%7}, {%8,%9}, {%0,%1,%2,%3};"
                        : "+f"(c[0]), "+f"(c[1]), "+f"(c[2]), "+f"(c[3])
                        : "r"(ah[mi].x), "r"(ah[mi].y), "r"(ah[mi].z), "r"(ah[mi].w),
                          "r"(bh[ni].x), "r"(bh[ni].y));
                    asm volatile(
                        "mma.sync.aligned.m16n8k8.row.col.f32.tf32.tf32.f32 "
                        "{%0,%1,%2,%3}, {%4,%5,%6,%7}, {%8,%9}, {%0,%1,%2,%3};"
                        : "+f"(c[0]), "+f"(c[1]), "+f"(c[2]), "+f"(c[3])
                        : "r"(al[mi].x), "r"(al[mi].y), "r"(al[mi].z), "r"(al[mi].w),
                          "r"(bh[ni].x), "r"(bh[ni].y));
                    asm volatile(
                        "mma.sync.aligned.m16n8k8.row.col.f32.tf32.tf32.f32 "
                        "{%0,%1,%2,%3}, {%4,%5,%6,%7}, {%8,%9}, {%0,%1,%2,%3};"
                        : "+f"(c[0]), "+f"(c[1]), "+f"(c[2]), "+f"(c[3])
                        : "r"(ah[mi].x), "r"(ah[mi].y), "r"(ah[mi].z), "r"(ah[mi].w),
                          "r"(bl[ni].x), "r"(bl[ni].y));
                }
        }
    }

    #pragma unroll
    for (int mi = 0; mi < 2; mi++)
        #pragma unroll
        for (int ni = 0; ni < 4; ni++) {
            int row0 = bm + wm * 32 + mi * 16 + gid;
            int col  = bn + wn * 32 + ni * 8 + tig * 2;
            float* c = acc[mi][ni];
            *(float2*)&g_u2[(size_t)row0 * RRR + col]       = make_float2(c[0], c[1]);
            *(float2*)&g_u2[(size_t)(row0 + 8) * RRR + col] = make_float2(c[2], c[3]);
        }
}
#define K2_SMEM_BYTES ((8 * ASS + 8 * BSS) * 4)

// ---------------------------------------------------------------------------
// Kernel 3: grid 4096. out = (u2·f2^T + s) * invw.
// ---------------------------------------------------------------------------
__global__ void __launch_bounds__(256) k3_stream(
    const float* __restrict__ out_f2,
    const void*  __restrict__ maskp,
    float* __restrict__ out)
{
    __shared__ float f2t[RK * CC];
    __shared__ float u2s[256];
    __shared__ float invw[32];

    const int tid = threadIdx.x;
    const int g = blockIdx.x >> 1, h = blockIdx.x & 1;

    if (tid < 64)
        ((float4*)u2s)[tid] = ((const float4*)(g_u2 + (size_t)g * RRR + h * 256))[tid];
    #pragma unroll
    for (int i = tid; i < RK * CC; i += 256) {
        int q = i >> 3, Cr = i & 7;
        f2t[Cr * CC + q] = out_f2[i];
    }
    if (tid < 32) {
        int ge2 = g_flags[0], odd = g_flags[1];
        int m = h * 32 + tid;
        int w;
        if (ge2) {
            const float* mf = (const float*)maskp + (size_t)g * 256;
            w = (mf[m] != 0.f ? 0 : 1) + (mf[m + 64] != 0.f ? 0 : 1)
              + (mf[m + 128] != 0.f ? 0 : 1) + (mf[m + 192] != 0.f ? 0 : 1);
        } else if (odd) {
            const unsigned char* mb = (const unsigned char*)maskp + (size_t)g * 256;
            w = (mb[m] ? 0 : 1) + (mb[m + 64] ? 0 : 1)
              + (mb[m + 128] ? 0 : 1) + (mb[m + 192] ? 0 : 1);
        } else {
            const int* mi = (const int*)maskp + (size_t)g * 256;
            w = (mi[m] ? 0 : 1) + (mi[m + 64] ? 0 : 1)
              + (mi[m + 128] ? 0 : 1) + (mi[m + 192] ? 0 : 1);
        }
        invw[tid] = (w > 0) ? 1.0f / ((float)w + 1e-10f) : 0.0f;
    }
    __syncthreads();

    const float4* sg = (const float4*)(g_s + (size_t)g * TOK + h * 4096);
    float4*       og = (float4*)(out + (size_t)g * TOK + h * 4096);
    #pragma unroll
    for (int it = 0; it < 4; it++) {
        int i  = tid + it * 256;
        int m  = i >> 5;
        int q0 = (i & 31) << 2;
        float4 sv = sg[i];
        float r0 = 0.f, r1 = 0.f, r2 = 0.f, r3 = 0.f;
        #pragma unroll
        for (int Cr = 0; Cr < 8; Cr++) {
            float u = u2s[m * 8 + Cr];
            float4 f = *(const float4*)&f2t[Cr * CC + q0];
            r0 += u * f.x; r1 += u * f.y; r2 += u * f.z; r3 += u * f.w;
        }
        float iw = invw[m];
        float4 ov;
        ov.x = (r0 + sv.x) * iw;
        ov.y = (r1 + sv.y) * iw;
        ov.z = (r2 + sv.z) * iw;
        ov.w = (r3 + sv.w) * iw;
        og[i] = ov;
    }
}

// ---------------------------------------------------------------------------
// inputs: 0:x 1:core 2:out_f0 3:out_f1 4:out_f2 5:in_f0 6:in_f1 7:in_f2 8:mask
// ---------------------------------------------------------------------------
extern "C" void kernel_launch(void* const* d_in, const int* in_sizes, int n_in,
                              void* d_out, int out_size)
{
    const float* x      = (const float*)d_in[0];
    const float* core   = (const float*)d_in[1];
    const float* out_f0 = (const float*)d_in[2];
    const float* out_f1 = (const float*)d_in[3];
    const float* out_f2 = (const float*)d_in[4];
    const float* in_f0  = (const float*)d_in[5];
    const float* in_f1  = (const float*)d_in[6];
    const float* in_f2  = (const float*)d_in[7];
    float* out = (float*)d_out;

    static bool attr_done = false;
    if (!attr_done) {
        cudaFuncSetAttribute(k2_core_gemm,
                             cudaFuncAttributeMaxDynamicSharedMemorySize,
                             K2_SMEM_BYTES);
        attr_done = true;
    }

    void* flags_ptr = nullptr;
    cudaGetSymbolAddress(&flags_ptr, g_flags);
    cudaMemsetAsync(flags_ptr, 0, 2 * sizeof(int));

    k0_scan_mask<<<64, 256>>>((const unsigned char*)d_in[8]);
    fold_w4<<<64, 256>>>(core, out_f0, out_f1, in_f0, in_f1);
    k1_reduce_project<<<2 * GROUPS, 256>>>(x, in_f2);
    dim3 g2(GROUPS / 128, RRR / 64);
    k2_core_gemm<<<g2, 256, K2_SMEM_BYTES>>>();
    k3_stream<<<2 * GROUPS, 256>>>(out_f2, d_in[8], out);
}

// round 8
// speedup vs baseline: 1.0354x; 1.0354x over previous
#include <cuda_runtime.h>
#include <cstdint>

#define GROUPS  2048
#define MM      64
#define CC      128
#define TOK     8192
#define RK      8
#define RRR     512
#define MASKN   524288

__device__ float g_s  [(size_t)GROUPS * TOK];  // 64 MB group sums
__device__ float g_t1h[(size_t)GROUPS * RRR];  // 4 MB  T1 hi (tf32)
__device__ float g_t1l[(size_t)GROUPS * RRR];  // 4 MB  T1 lo (tf32)
__device__ float g_u2 [(size_t)GROUPS * RRR];  // 4 MB
__device__ float g_w4h[RRR * RRR];             // 1 MB  W4 hi
__device__ float g_w4l[RRR * RRR];             // 1 MB  W4 lo
__device__ int   g_flags[2];                   // [ge2, odd]

__device__ __forceinline__ void tf32_split(float v, float& hi, float& lo)
{
    unsigned hb, lb;
    asm("cvt.rna.tf32.f32 %0, %1;" : "=r"(hb) : "f"(v));
    hi = __uint_as_float(hb);
    float r = v - hi;
    asm("cvt.rna.tf32.f32 %0, %1;" : "=r"(lb) : "f"(r));
    lo = __uint_as_float(lb);
}

// ---------------------------------------------------------------------------
// Mask dtype scan
// ---------------------------------------------------------------------------
__global__ void __launch_bounds__(256) k0_scan_mask(const unsigned char* __restrict__ mask)
{
    const uint4* p = (const uint4*)mask;
    unsigned acc = 0;
    int i = blockIdx.x * 256 + threadIdx.x;
    for (; i < MASKN / 16; i += 64 * 256) {
        uint4 v = p[i];
        acc |= (v.x | v.y | v.z | v.w);
    }
    __shared__ unsigned sacc;
    if (threadIdx.x == 0) sacc = 0;
    __syncthreads();
    #pragma unroll
    for (int off = 16; off >= 1; off >>= 1)
        acc |= __shfl_xor_sync(0xffffffffu, acc, off);
    if ((threadIdx.x & 31) == 0) atomicOr(&sacc, acc);
    __syncthreads();
    if (threadIdx.x == 0) {
        unsigned a = sacc;
        if (a & 0xFEFEFEFEu) atomicOr(&g_flags[0], 1);
        if (a & 0xFFFFFF00u) atomicOr(&g_flags[1], 1);
    }
}

// ---------------------------------------------------------------------------
// Fold: W4[(o,p,C),(a,d,F)] -> hi/lo tf32 pair. 64 blocks.
// ---------------------------------------------------------------------------
__global__ void __launch_bounds__(256) fold_w4(
    const float* __restrict__ core,
    const float* __restrict__ of0, const float* __restrict__ of1,
    const float* __restrict__ if0, const float* __restrict__ if1)
{
    __shared__ float bufA[4096], bufB[4096];
    __shared__ float sf[4][64];
    const int tid = threadIdx.x;
    const int C = blockIdx.x >> 3, F = blockIdx.x & 7;

    if (tid < 64)       sf[0][tid]       = of0[tid];
    else if (tid < 128) sf[1][tid - 64]  = of1[tid - 64];
    else if (tid < 192) sf[2][tid - 128] = if0[tid - 128];
    else                sf[3][tid - 192] = if1[tid - 192];

    #pragma unroll
    for (int i = tid; i < 4096; i += 256) {
        int A = i >> 9, B = (i >> 6) & 7, D = (i >> 3) & 7, E = i & 7;
        bufA[i] = core[A * 32768 + B * 4096 + C * 512 + D * 64 + E * 8 + F];
    }
    __syncthreads();
    #pragma unroll
    for (int i = tid; i < 4096; i += 256) {   // M1[A,B,D,d] = sum_E K * if1[d,E]
        int ABD = i >> 3, d = i & 7;
        float acc = 0.f;
        #pragma unroll
        for (int E = 0; E < 8; E++) acc += bufA[ABD * 8 + E] * sf[3][d * 8 + E];
        bufB[i] = acc;
    }
    __syncthreads();
    #pragma unroll
    for (int i = tid; i < 4096; i += 256) {   // M2[A,B,d,a] = sum_D M1 * if0[a,D]
        int AB = i >> 6, d = (i >> 3) & 7, a = i & 7;
        float acc = 0.f;
        #pragma unroll
        for (int D = 0; D < 8; D++) acc += bufB[(AB * 8 + D) * 8 + d] * sf[2][a * 8 + D];
        bufA[i] = acc;
    }
    __syncthreads();
    #pragma unroll
    for (int i = tid; i < 4096; i += 256) {   // M3[B,d,a,o] = sum_A M2 * of0[o,A]
        int B = i >> 9, d = (i >> 6) & 7, a = (i >> 3) & 7, o = i & 7;
        float acc = 0.f;
        #pragma unroll
        for (int A = 0; A < 8; A++)
            acc += bufA[((A * 8 + B) * 8 + d) * 8 + a] * sf[0][o * 8 + A];
        bufB[i] = acc;
    }
    __syncthreads();
    #pragma unroll
    for (int i = tid; i < 4096; i += 256) {   // W4 = sum_B M3 * of1[p,B]
        int o = i >> 9, p = (i >> 6) & 7, a = (i >> 3) & 7, d = i & 7;
        float acc = 0.f;
        #pragma unroll
        for (int B = 0; B < 8; B++)
            acc += bufB[((B * 8 + d) * 8 + a) * 8 + o] * sf[1][p * 8 + B];
        float hi, lo;
        tf32_split(acc, hi, lo);
        size_t idx = (size_t)((o * 8 + p) * 8 + C) * RRR + a * 64 + d * 8 + F;
        g_w4h[idx] = hi;
        g_w4l[idx] = lo;
    }
}

// ---------------------------------------------------------------------------
// Kernel 1: grid 4096 (half-group per block): s -> scratch, T1 hi/lo.
// ---------------------------------------------------------------------------
__global__ void __launch_bounds__(256) k1_reduce_project(
    const float* __restrict__ x,
    const float* __restrict__ in_f2)   // (128,8)
{
    __shared__ float s[32 * 129];
    __shared__ float f2s[CC * RK];

    const int tid = threadIdx.x;
    const int g = blockIdx.x >> 1, h = blockIdx.x & 1;
    const size_t base = (size_t)g * (4 * TOK) + h * 4096;

    #pragma unroll
    for (int i = tid; i < CC * RK; i += 256) f2s[i] = in_f2[i];

    const float4* xb = (const float4*)(x + base);
    float4*       sg = (float4*)(g_s + (size_t)g * TOK + h * 4096);
    #pragma unroll
    for (int it = 0; it < 4; it++) {
        int i = tid + it * 256;
        float4 v0 = xb[i];
        float4 v1 = xb[i + 2048];
        float4 v2 = xb[i + 4096];
        float4 v3 = xb[i + 6144];
        float4 r;
        r.x = (v0.x + v1.x) + (v2.x + v3.x);
        r.y = (v0.y + v1.y) + (v2.y + v3.y);
        r.z = (v0.z + v1.z) + (v2.z + v3.z);
        r.w = (v0.w + v1.w) + (v2.w + v3.w);
        sg[i] = r;
        int m = i >> 5;
        int e = (i & 31) << 2;
        float* sp = &s[m * 129 + e];
        sp[0] = r.x; sp[1] = r.y; sp[2] = r.z; sp[3] = r.w;
    }
    __syncthreads();
    {
        int m = tid & 31;
        int F = tid >> 5;
        float acc = 0.f;
        const float* srow = &s[m * 129];
        #pragma unroll 8
        for (int e = 0; e < CC; e++)
            acc += srow[e] * f2s[e * RK + F];
        float hi, lo;
        tf32_split(acc, hi, lo);
        size_t idx = (size_t)g * RRR + (h * 32 + m) * 8 + F;
        g_t1h[idx] = hi;
        g_t1l[idx] = lo;
    }
}

// ---------------------------------------------------------------------------
// Kernel 2: U2 = T1 @ W4^T via mma.m16n8k8.tf32, 3xTF32 split.
// BM=64 BN=64 BK=32, 256 thr, warps 2(m)x4(n), warp tile 32x16.
// grid = (32, 8) = 256 blocks (2 co-resident blocks/SM, one wave).
// Register-prefetch double buffering: next iter's LDGs overlap MMA stage.
// ---------------------------------------------------------------------------
#define ASS 520     // 4 m16-tiles x 128 + 8 pad
#define BSS 520     // 8 n8-tiles  x 64  + 8 pad
__global__ void __launch_bounds__(256) k2_core_gemm()
{
    __shared__ __align__(16) float Ah[4 * ASS], Al[4 * ASS];
    __shared__ __align__(16) float Bh[4 * BSS], Bl[4 * BSS];

    const int tid  = threadIdx.x;
    const int lane = tid & 31;
    const int wid  = tid >> 5;
    const int wm   = wid >> 2;          // 0..1 -> m offset wm*32
    const int wn   = wid & 3;           // 0..3 -> n offset wn*16
    const int gid  = lane >> 2;
    const int tig  = lane & 3;
    const int bm   = blockIdx.x * 64;
    const int bn   = blockIdx.y * 64;

    // staging index math (per thread, l = 0,1)
    int row[2], c4[2], sA[2], sB[2];
    #pragma unroll
    for (int l = 0; l < 2; l++) {
        int fidx = tid + l * 256;          // 512 float4 per operand
        row[l] = fidx >> 3;                // 0..63
        c4[l]  = (fidx & 7) << 2;          // 0..28
        int mt = row[l] >> 4, tr = row[l] & 15;
        int ks = c4[l] >> 3;
        int regA = (tr >> 3) + (((c4[l] & 7) >> 2) << 1);
        sA[l] = ks * ASS + mt * 128 + (tr & 7) * 16 + regA;
        int nt = row[l] >> 3, tn = row[l] & 7;
        int regB = (c4[l] >> 2) & 1;
        sB[l] = ks * BSS + nt * 64 + tn * 8 + regB;
    }

    float4 pah[2], pal[2], pbh[2], pbl[2];
    #pragma unroll
    for (int l = 0; l < 2; l++) {
        pah[l] = *(const float4*)(g_t1h + (size_t)(bm + row[l]) * RRR + c4[l]);
        pal[l] = *(const float4*)(g_t1l + (size_t)(bm + row[l]) * RRR + c4[l]);
        pbh[l] = *(const float4*)(g_w4h + (size_t)(bn + row[l]) * RRR + c4[l]);
        pbl[l] = *(const float4*)(g_w4l + (size_t)(bn + row[l]) * RRR + c4[l]);
    }

    float acc[2][2][4];
    #pragma unroll
    for (int mi = 0; mi < 2; mi++)
        #pragma unroll
        for (int ni = 0; ni < 2; ni++)
            #pragma unroll
            for (int r = 0; r < 4; r++) acc[mi][ni][r] = 0.f;

    for (int it = 0; it < 16; it++) {
        // ---- store prefetched regs into fragment-permuted smem ----
        #pragma unroll
        for (int l = 0; l < 2; l++) {
            Ah[sA[l]]      = pah[l].x; Ah[sA[l] + 4]  = pah[l].y;
            Ah[sA[l] + 8]  = pah[l].z; Ah[sA[l] + 12] = pah[l].w;
            Al[sA[l]]      = pal[l].x; Al[sA[l] + 4]  = pal[l].y;
            Al[sA[l] + 8]  = pal[l].z; Al[sA[l] + 12] = pal[l].w;
            Bh[sB[l]]      = pbh[l].x; Bh[sB[l] + 2]  = pbh[l].y;
            Bh[sB[l] + 4]  = pbh[l].z; Bh[sB[l] + 6]  = pbh[l].w;
            Bl[sB[l]]      = pbl[l].x; Bl[sB[l] + 2]  = pbl[l].y;
            Bl[sB[l] + 4]  = pbl[l].z; Bl[sB[l] + 6]  = pbl[l].w;
        }
        __syncthreads();

        // ---- prefetch next iteration (overlaps MMA stage below) ----
        if (it < 15) {
            int k0 = (it + 1) * 32;
            #pragma unroll
            for (int l = 0; l < 2; l++) {
                pah[l] = *(const float4*)(g_t1h + (size_t)(bm + row[l]) * RRR + k0 + c4[l]);
                pal[l] = *(const float4*)(g_t1l + (size_t)(bm + row[l]) * RRR + k0 + c4[l]);
                pbh[l] = *(const float4*)(g_w4h + (size_t)(bn + row[l]) * RRR + k0 + c4[l]);
                pbl[l] = *(const float4*)(g_w4l + (size_t)(bn + row[l]) * RRR + k0 + c4[l]);
            }
        }

        // ---- MMA stage ----
        #pragma unroll
        for (int ks = 0; ks < 4; ks++) {
            uint4 ah[2], al[2];
            uint2 bh[2], bl[2];
            #pragma unroll
            for (int mi = 0; mi < 2; mi++) {
                int mt = wm * 2 + mi;
                ah[mi] = *(const uint4*)&Ah[ks * ASS + mt * 128 + lane * 4];
                al[mi] = *(const uint4*)&Al[ks * ASS + mt * 128 + lane * 4];
            }
            #pragma unroll
            for (int ni = 0; ni < 2; ni++) {
                int nt = wn * 2 + ni;
                bh[ni] = *(const uint2*)&Bh[ks * BSS + nt * 64 + lane * 2];
                bl[ni] = *(const uint2*)&Bl[ks * BSS + nt * 64 + lane * 2];
            }
            #pragma unroll
            for (int mi = 0; mi < 2; mi++)
                #pragma unroll
                for (int ni = 0; ni < 2; ni++) {
                    float* c = acc[mi][ni];
                    asm volatile(
                        "mma.sync.aligned.m16n8k8.row.col.f32.tf32.tf32.f32 "
                        "{%0,%1,%2,%3}, {%4,%5,%6,%7}, {%8,%9}, {%0,%1,%2,%3};"
                        : "+f"(c[0]), "+f"(c[1]), "+f"(c[2]), "+f"(c[3])
                        : "r"(ah[mi].x), "r"(ah[mi].y), "r"(ah[mi].z), "r"(ah[mi].w),
                          "r"(bh[ni].x), "r"(bh[ni].y));
                    asm volatile(
                        "mma.sync.aligned.m16n8k8.row.col.f32.tf32.tf32.f32 "
                        "{%0,%1,%2,%3}, {%4,%5,%6,%7}, {%8,%9}, {%0,%1,%2,%3};"
                        : "+f"(c[0]), "+f"(c[1]), "+f"(c[2]), "+f"(c[3])
                        : "r"(al[mi].x), "r"(al[mi].y), "r"(al[mi].z), "r"(al[mi].w),
                          "r"(bh[ni].x), "r"(bh[ni].y));
                    asm volatile(
                        "mma.sync.aligned.m16n8k8.row.col.f32.tf32.tf32.f32 "
                        "{%0,%1,%2,%3}, {%4,%5,%6,%7}, {%8,%9}, {%0,%1,%2,%3};"
                        : "+f"(c[0]), "+f"(c[1]), "+f"(c[2]), "+f"(c[3])
                        : "r"(ah[mi].x), "r"(ah[mi].y), "r"(ah[mi].z), "r"(ah[mi].w),
                          "r"(bl[ni].x), "r"(bl[ni].y));
                }
        }
        __syncthreads();
    }

    #pragma unroll
    for (int mi = 0; mi < 2; mi++)
        #pragma unroll
        for (int ni = 0; ni < 2; ni++) {
            int row0 = bm + wm * 32 + mi * 16 + gid;
            int col  = bn + wn * 16 + ni * 8 + tig * 2;
            float* c = acc[mi][ni];
            *(float2*)&g_u2[(size_t)row0 * RRR + col]       = make_float2(c[0], c[1]);
            *(float2*)&g_u2[(size_t)(row0 + 8) * RRR + col] = make_float2(c[2], c[3]);
        }
}

// ---------------------------------------------------------------------------
// Kernel 3: grid 4096. out = (u2·f2^T + s) * invw.
// ---------------------------------------------------------------------------
__global__ void __launch_bounds__(256) k3_stream(
    const float* __restrict__ out_f2,
    const void*  __restrict__ maskp,
    float* __restrict__ out)
{
    __shared__ float f2t[RK * CC];
    __shared__ float u2s[256];
    __shared__ float invw[32];

    const int tid = threadIdx.x;
    const int g = blockIdx.x >> 1, h = blockIdx.x & 1;

    if (tid < 64)
        ((float4*)u2s)[tid] = ((const float4*)(g_u2 + (size_t)g * RRR + h * 256))[tid];
    #pragma unroll
    for (int i = tid; i < RK * CC; i += 256) {
        int q = i >> 3, Cr = i & 7;
        f2t[Cr * CC + q] = out_f2[i];
    }
    if (tid < 32) {
        int ge2 = g_flags[0], odd = g_flags[1];
        int m = h * 32 + tid;
        int w;
        if (ge2) {
            const float* mf = (const float*)maskp + (size_t)g * 256;
            w = (mf[m] != 0.f ? 0 : 1) + (mf[m + 64] != 0.f ? 0 : 1)
              + (mf[m + 128] != 0.f ? 0 : 1) + (mf[m + 192] != 0.f ? 0 : 1);
        } else if (odd) {
            const unsigned char* mb = (const unsigned char*)maskp + (size_t)g * 256;
            w = (mb[m] ? 0 : 1) + (mb[m + 64] ? 0 : 1)
              + (mb[m + 128] ? 0 : 1) + (mb[m + 192] ? 0 : 1);
        } else {
            const int* mi = (const int*)maskp + (size_t)g * 256;
            w = (mi[m] ? 0 : 1) + (mi[m + 64] ? 0 : 1)
              + (mi[m + 128] ? 0 : 1) + (mi[m + 192] ? 0 : 1);
        }
        invw[tid] = (w > 0) ? 1.0f / ((float)w + 1e-10f) : 0.0f;
    }
    __syncthreads();

    const float4* sg = (const float4*)(g_s + (size_t)g * TOK + h * 4096);
    float4*       og = (float4*)(out + (size_t)g * TOK + h * 4096);
    #pragma unroll
    for (int it = 0; it < 4; it++) {
        int i  = tid + it * 256;
        int m  = i >> 5;
        int q0 = (i & 31) << 2;
        float4 sv = sg[i];
        float r0 = 0.f, r1 = 0.f, r2 = 0.f, r3 = 0.f;
        #pragma unroll
        for (int Cr = 0; Cr < 8; Cr++) {
            float u = u2s[m * 8 + Cr];
            float4 f = *(const float4*)&f2t[Cr * CC + q0];
            r0 += u * f.x; r1 += u * f.y; r2 += u * f.z; r3 += u * f.w;
        }
        float iw = invw[m];
        float4 ov;
        ov.x = (r0 + sv.x) * iw;
        ov.y = (r1 + sv.y) * iw;
        ov.z = (r2 + sv.z) * iw;
        ov.w = (r3 + sv.w) * iw;
        og[i] = ov;
    }
}

// ---------------------------------------------------------------------------
// inputs: 0:x 1:core 2:out_f0 3:out_f1 4:out_f2 5:in_f0 6:in_f1 7:in_f2 8:mask
// ---------------------------------------------------------------------------
extern "C" void kernel_launch(void* const* d_in, const int* in_sizes, int n_in,
                              void* d_out, int out_size)
{
    const float* x      = (const float*)d_in[0];
    const float* core   = (const float*)d_in[1];
    const float* out_f0 = (const float*)d_in[2];
    const float* out_f1 = (const float*)d_in[3];
    const float* out_f2 = (const float*)d_in[4];
    const float* in_f0  = (const float*)d_in[5];
    const float* in_f1  = (const float*)d_in[6];
    const float* in_f2  = (const float*)d_in[7];
    float* out = (float*)d_out;

    void* flags_ptr = nullptr;
    cudaGetSymbolAddress(&flags_ptr, g_flags);
    cudaMemsetAsync(flags_ptr, 0, 2 * sizeof(int));

    k0_scan_mask<<<64, 256>>>((const unsigned char*)d_in[8]);
    fold_w4<<<64, 256>>>(core, out_f0, out_f1, in_f0, in_f1);
    k1_reduce_project<<<2 * GROUPS, 256>>>(x, in_f2);
    dim3 g2(GROUPS / 64, RRR / 64);
    k2_core_gemm<<<g2, 256>>>();
    k3_stream<<<2 * GROUPS, 256>>>(out_f2, d_in[8], out);
}

// round 9
// speedup vs baseline: 1.0360x; 1.0006x over previous
#include <cuda_runtime.h>
#include <cstdint>

#define GROUPS  2048
#define MM      64
#define CC      128
#define TOK     8192
#define RK      8
#define RRR     512
#define MASKN   524288

// Fragment-permuted operand storage:
//  A (T1, 2048x512): tile (mt,ks) = 16x8, stored [mt][ks][128]; element (tr,tc)
//      at lane=(tr&7)*4+(tc&3), reg=(tr>>3)+((tc>>2)<<1); float at tile*128+lane*4+reg
//  B (W4, 512x512):  tile (nt,ks) = 8x8,  stored [nt][ks][64];  element (n,k)
//      at lane=(n&7)*4+(k&3),  reg=k>>2;  float at tile*64+lane*2+reg
__device__ float g_s  [(size_t)GROUPS * TOK];  // 64 MB group sums
__device__ float g_t1h[(size_t)GROUPS * RRR];  // 4 MB  T1 hi (permuted)
__device__ float g_t1l[(size_t)GROUPS * RRR];  // 4 MB  T1 lo (permuted)
__device__ float g_u2 [(size_t)GROUPS * RRR];  // 4 MB
__device__ float g_w4h[RRR * RRR];             // 1 MB  W4 hi (permuted)
__device__ float g_w4l[RRR * RRR];             // 1 MB  W4 lo (permuted)
__device__ int   g_flags[2];                   // [ge2, odd]

__device__ __forceinline__ void tf32_split(float v, float& hi, float& lo)
{
    unsigned hb, lb;
    asm("cvt.rna.tf32.f32 %0, %1;" : "=r"(hb) : "f"(v));
    hi = __uint_as_float(hb);
    float r = v - hi;
    asm("cvt.rna.tf32.f32 %0, %1;" : "=r"(lb) : "f"(r));
    lo = __uint_as_float(lb);
}

__device__ __forceinline__ size_t a_perm_idx(int gr, int c)
{
    int mt = gr >> 4, tr = gr & 15;
    int ks = c >> 3,  tc = c & 7;
    int lane = (tr & 7) * 4 + (tc & 3);
    int reg  = (tr >> 3) + ((tc >> 2) << 1);
    return (size_t)(mt * 64 + ks) * 128 + lane * 4 + reg;
}
__device__ __forceinline__ size_t b_perm_idx(int n, int k)
{
    int nt = n >> 3, gid = n & 7;
    int ks = k >> 3, kc = k & 7;
    int lane = gid * 4 + (kc & 3);
    int reg  = kc >> 2;
    return (size_t)(nt * 64 + ks) * 64 + lane * 2 + reg;
}

// ---------------------------------------------------------------------------
// Mask dtype scan
// ---------------------------------------------------------------------------
__global__ void __launch_bounds__(256) k0_scan_mask(const unsigned char* __restrict__ mask)
{
    const uint4* p = (const uint4*)mask;
    unsigned acc = 0;
    int i = blockIdx.x * 256 + threadIdx.x;
    for (; i < MASKN / 16; i += 64 * 256) {
        uint4 v = p[i];
        acc |= (v.x | v.y | v.z | v.w);
    }
    __shared__ unsigned sacc;
    if (threadIdx.x == 0) sacc = 0;
    __syncthreads();
    #pragma unroll
    for (int off = 16; off >= 1; off >>= 1)
        acc |= __shfl_xor_sync(0xffffffffu, acc, off);
    if ((threadIdx.x & 31) == 0) atomicOr(&sacc, acc);
    __syncthreads();
    if (threadIdx.x == 0) {
        unsigned a = sacc;
        if (a & 0xFEFEFEFEu) atomicOr(&g_flags[0], 1);
        if (a & 0xFFFFFF00u) atomicOr(&g_flags[1], 1);
    }
}

// ---------------------------------------------------------------------------
// Fold: W4[(o,p,C),(a,d,F)] -> hi/lo tf32, written fragment-permuted.
// ---------------------------------------------------------------------------
__global__ void __launch_bounds__(256) fold_w4(
    const float* __restrict__ core,
    const float* __restrict__ of0, const float* __restrict__ of1,
    const float* __restrict__ if0, const float* __restrict__ if1)
{
    __shared__ float bufA[4096], bufB[4096];
    __shared__ float sf[4][64];
    const int tid = threadIdx.x;
    const int C = blockIdx.x >> 3, F = blockIdx.x & 7;

    if (tid < 64)       sf[0][tid]       = of0[tid];
    else if (tid < 128) sf[1][tid - 64]  = of1[tid - 64];
    else if (tid < 192) sf[2][tid - 128] = if0[tid - 128];
    else                sf[3][tid - 192] = if1[tid - 192];

    #pragma unroll
    for (int i = tid; i < 4096; i += 256) {
        int A = i >> 9, B = (i >> 6) & 7, D = (i >> 3) & 7, E = i & 7;
        bufA[i] = core[A * 32768 + B * 4096 + C * 512 + D * 64 + E * 8 + F];
    }
    __syncthreads();
    #pragma unroll
    for (int i = tid; i < 4096; i += 256) {   // M1[A,B,D,d] = sum_E K * if1[d,E]
        int ABD = i >> 3, d = i & 7;
        float acc = 0.f;
        #pragma unroll
        for (int E = 0; E < 8; E++) acc += bufA[ABD * 8 + E] * sf[3][d * 8 + E];
        bufB[i] = acc;
    }
    __syncthreads();
    #pragma unroll
    for (int i = tid; i < 4096; i += 256) {   // M2[A,B,d,a] = sum_D M1 * if0[a,D]
        int AB = i >> 6, d = (i >> 3) & 7, a = i & 7;
        float acc = 0.f;
        #pragma unroll
        for (int D = 0; D < 8; D++) acc += bufB[(AB * 8 + D) * 8 + d] * sf[2][a * 8 + D];
        bufA[i] = acc;
    }
    __syncthreads();
    #pragma unroll
    for (int i = tid; i < 4096; i += 256) {   // M3[B,d,a,o] = sum_A M2 * of0[o,A]
        int B = i >> 9, d = (i >> 6) & 7, a = (i >> 3) & 7, o = i & 7;
        float acc = 0.f;
        #pragma unroll
        for (int A = 0; A < 8; A++)
            acc += bufA[((A * 8 + B) * 8 + d) * 8 + a] * sf[0][o * 8 + A];
        bufB[i] = acc;
    }
    __syncthreads();
    #pragma unroll
    for (int i = tid; i < 4096; i += 256) {   // W4 = sum_B M3 * of1[p,B]
        int o = i >> 9, p = (i >> 6) & 7, a = (i >> 3) & 7, d = i & 7;
        float acc = 0.f;
        #pragma unroll
        for (int B = 0; B < 8; B++)
            acc += bufB[((B * 8 + d) * 8 + a) * 8 + o] * sf[1][p * 8 + B];
        float hi, lo;
        tf32_split(acc, hi, lo);
        int n = (o * 8 + p) * 8 + C;
        int k = a * 64 + d * 8 + F;
        size_t idx = b_perm_idx(n, k);
        g_w4h[idx] = hi;
        g_w4l[idx] = lo;
    }
}

// ---------------------------------------------------------------------------
// Kernel 1: grid 4096 (half-group per block): s -> scratch, T1 hi/lo permuted.
// ---------------------------------------------------------------------------
__global__ void __launch_bounds__(256) k1_reduce_project(
    const float* __restrict__ x,
    const float* __restrict__ in_f2)   // (128,8)
{
    __shared__ float s[32 * 129];
    __shared__ float f2s[CC * RK];

    const int tid = threadIdx.x;
    const int g = blockIdx.x >> 1, h = blockIdx.x & 1;
    const size_t base = (size_t)g * (4 * TOK) + h * 4096;

    #pragma unroll
    for (int i = tid; i < CC * RK; i += 256) f2s[i] = in_f2[i];

    const float4* xb = (const float4*)(x + base);
    float4*       sg = (float4*)(g_s + (size_t)g * TOK + h * 4096);
    #pragma unroll
    for (int it = 0; it < 4; it++) {
        int i = tid + it * 256;
        float4 v0 = xb[i];
        float4 v1 = xb[i + 2048];
        float4 v2 = xb[i + 4096];
        float4 v3 = xb[i + 6144];
        float4 r;
        r.x = (v0.x + v1.x) + (v2.x + v3.x);
        r.y = (v0.y + v1.y) + (v2.y + v3.y);
        r.z = (v0.z + v1.z) + (v2.z + v3.z);
        r.w = (v0.w + v1.w) + (v2.w + v3.w);
        sg[i] = r;
        int m = i >> 5;
        int e = (i & 31) << 2;
        float* sp = &s[m * 129 + e];
        sp[0] = r.x; sp[1] = r.y; sp[2] = r.z; sp[3] = r.w;
    }
    __syncthreads();
    {
        int m = tid & 31;
        int F = tid >> 5;
        float acc = 0.f;
        const float* srow = &s[m * 129];
        #pragma unroll 8
        for (int e = 0; e < CC; e++)
            acc += srow[e] * f2s[e * RK + F];
        float hi, lo;
        tf32_split(acc, hi, lo);
        size_t idx = a_perm_idx(g, (h * 32 + m) * 8 + F);
        g_t1h[idx] = hi;
        g_t1l[idx] = lo;
    }
}

// ---------------------------------------------------------------------------
// Kernel 2: U2 = T1 @ W4^T — fragment-direct, NO shared memory.
// BM=64 BN=64, 256 thr, warps 2(m)x4(n), warp tile 32x16, 3xTF32.
// grid = (32, 8). Register double-buffer over 64 k8-slabs.
// ---------------------------------------------------------------------------
__global__ void __launch_bounds__(256) k2_core_gemm()
{
    const int tid  = threadIdx.x;
    const int lane = tid & 31;
    const int wid  = tid >> 5;
    const int wm   = wid >> 2;          // 0..1
    const int wn   = wid & 3;           // 0..3
    const int gid  = lane >> 2;
    const int tig  = lane & 3;
    const int bm   = blockIdx.x * 64;
    const int bn   = blockIdx.y * 64;

    // A tiles: mt = bm/16 + wm*2 + {0,1};  B tiles: nt = bn/8 + wn*2 + {0,1}
    const float* pAh = g_t1h + (size_t)((bm >> 4) + wm * 2) * 64 * 128 + lane * 4;
    const float* pAl = g_t1l + (size_t)((bm >> 4) + wm * 2) * 64 * 128 + lane * 4;
    const float* pBh = g_w4h + (size_t)((bn >> 3) + wn * 2) * 64 * 64 + lane * 2;
    const float* pBl = g_w4l + (size_t)((bn >> 3) + wn * 2) * 64 * 64 + lane * 2;

    float acc[2][2][4];
    #pragma unroll
    for (int mi = 0; mi < 2; mi++)
        #pragma unroll
        for (int ni = 0; ni < 2; ni++)
            #pragma unroll
            for (int r = 0; r < 4; r++) acc[mi][ni][r] = 0.f;

    uint4 ah[2][2], al[2][2];
    uint2 bh[2][2], bl[2][2];

    // prefetch slab 0
    #pragma unroll
    for (int mi = 0; mi < 2; mi++) {
        ah[0][mi] = *(const uint4*)(pAh + (size_t)mi * 64 * 128);
        al[0][mi] = *(const uint4*)(pAl + (size_t)mi * 64 * 128);
    }
    #pragma unroll
    for (int ni = 0; ni < 2; ni++) {
        bh[0][ni] = *(const uint2*)(pBh + (size_t)ni * 64 * 64);
        bl[0][ni] = *(const uint2*)(pBl + (size_t)ni * 64 * 64);
    }

    #pragma unroll 4
    for (int ks = 0; ks < 64; ks++) {
        int cur = ks & 1, nxt = cur ^ 1;
        if (ks < 63) {
            size_t oa = (size_t)(ks + 1) * 128;
            size_t ob = (size_t)(ks + 1) * 64;
            #pragma unroll
            for (int mi = 0; mi < 2; mi++) {
                ah[nxt][mi] = *(const uint4*)(pAh + (size_t)mi * 64 * 128 + oa);
                al[nxt][mi] = *(const uint4*)(pAl + (size_t)mi * 64 * 128 + oa);
            }
            #pragma unroll
            for (int ni = 0; ni < 2; ni++) {
                bh[nxt][ni] = *(const uint2*)(pBh + (size_t)ni * 64 * 64 + ob);
                bl[nxt][ni] = *(const uint2*)(pBl + (size_t)ni * 64 * 64 + ob);
            }
        }
        #pragma unroll
        for (int mi = 0; mi < 2; mi++)
            #pragma unroll
            for (int ni = 0; ni < 2; ni++) {
                float* c = acc[mi][ni];
                asm volatile(
                    "mma.sync.aligned.m16n8k8.row.col.f32.tf32.tf32.f32 "
                    "{%0,%1,%2,%3}, {%4,%5,%6,%7}, {%8,%9}, {%0,%1,%2,%3};"
                    : "+f"(c[0]), "+f"(c[1]), "+f"(c[2]), "+f"(c[3])
                    : "r"(ah[cur][mi].x), "r"(ah[cur][mi].y),
                      "r"(ah[cur][mi].z), "r"(ah[cur][mi].w),
                      "r"(bh[cur][ni].x), "r"(bh[cur][ni].y));
                asm volatile(
                    "mma.sync.aligned.m16n8k8.row.col.f32.tf32.tf32.f32 "
                    "{%0,%1,%2,%3}, {%4,%5,%6,%7}, {%8,%9}, {%0,%1,%2,%3};"
                    : "+f"(c[0]), "+f"(c[1]), "+f"(c[2]), "+f"(c[3])
                    : "r"(al[cur][mi].x), "r"(al[cur][mi].y),
                      "r"(al[cur][mi].z), "r"(al[cur][mi].w),
                      "r"(bh[cur][ni].x), "r"(bh[cur][ni].y));
                asm volatile(
                    "mma.sync.aligned.m16n8k8.row.col.f32.tf32.tf32.f32 "
                    "{%0,%1,%2,%3}, {%4,%5,%6,%7}, {%8,%9}, {%0,%1,%2,%3};"
                    : "+f"(c[0]), "+f"(c[1]), "+f"(c[2]), "+f"(c[3])
                    : "r"(ah[cur][mi].x), "r"(ah[cur][mi].y),
                      "r"(ah[cur][mi].z), "r"(ah[cur][mi].w),
                      "r"(bl[cur][ni].x), "r"(bl[cur][ni].y));
            }
    }

    #pragma unroll
    for (int mi = 0; mi < 2; mi++)
        #pragma unroll
        for (int ni = 0; ni < 2; ni++) {
            int row0 = bm + wm * 32 + mi * 16 + gid;
            int col  = bn + wn * 16 + ni * 8 + tig * 2;
            float* c = acc[mi][ni];
            *(float2*)&g_u2[(size_t)row0 * RRR + col]       = make_float2(c[0], c[1]);
            *(float2*)&g_u2[(size_t)(row0 + 8) * RRR + col] = make_float2(c[2], c[3]);
        }
}

// ---------------------------------------------------------------------------
// Kernel 3: grid 4096. out = (u2·f2^T + s) * invw.
// ---------------------------------------------------------------------------
__global__ void __launch_bounds__(256) k3_stream(
    const float* __restrict__ out_f2,
    const void*  __restrict__ maskp,
    float* __restrict__ out)
{
    __shared__ float f2t[RK * CC];
    __shared__ float u2s[256];
    __shared__ float invw[32];

    const int tid = threadIdx.x;
    const int g = blockIdx.x >> 1, h = blockIdx.x & 1;

    if (tid < 64)
        ((float4*)u2s)[tid] = ((const float4*)(g_u2 + (size_t)g * RRR + h * 256))[tid];
    #pragma unroll
    for (int i = tid; i < RK * CC; i += 256) {
        int q = i >> 3, Cr = i & 7;
        f2t[Cr * CC + q] = out_f2[i];
    }
    if (tid < 32) {
        int ge2 = g_flags[0], odd = g_flags[1];
        int m = h * 32 + tid;
        int w;
        if (ge2) {
            const float* mf = (const float*)maskp + (size_t)g * 256;
            w = (mf[m] != 0.f ? 0 : 1) + (mf[m + 64] != 0.f ? 0 : 1)
              + (mf[m + 128] != 0.f ? 0 : 1) + (mf[m + 192] != 0.f ? 0 : 1);
        } else if (odd) {
            const unsigned char* mb = (const unsigned char*)maskp + (size_t)g * 256;
            w = (mb[m] ? 0 : 1) + (mb[m + 64] ? 0 : 1)
              + (mb[m + 128] ? 0 : 1) + (mb[m + 192] ? 0 : 1);
        } else {
            const int* mi = (const int*)maskp + (size_t)g * 256;
            w = (mi[m] ? 0 : 1) + (mi[m + 64] ? 0 : 1)
              + (mi[m + 128] ? 0 : 1) + (mi[m + 192] ? 0 : 1);
        }
        invw[tid] = (w > 0) ? 1.0f / ((float)w + 1e-10f) : 0.0f;
    }
    __syncthreads();

    const float4* sg = (const float4*)(g_s + (size_t)g * TOK + h * 4096);
    float4*       og = (float4*)(out + (size_t)g * TOK + h * 4096);
    #pragma unroll
    for (int it = 0; it < 4; it++) {
        int i  = tid + it * 256;
        int m  = i >> 5;
        int q0 = (i & 31) << 2;
        float4 sv = sg[i];
        float r0 = 0.f, r1 = 0.f, r2 = 0.f, r3 = 0.f;
        #pragma unroll
        for (int Cr = 0; Cr < 8; Cr++) {
            float u = u2s[m * 8 + Cr];
            float4 f = *(const float4*)&f2t[Cr * CC + q0];
            r0 += u * f.x; r1 += u * f.y; r2 += u * f.z; r3 += u * f.w;
        }
        float iw = invw[m];
        float4 ov;
        ov.x = (r0 + sv.x) * iw;
        ov.y = (r1 + sv.y) * iw;
        ov.z = (r2 + sv.z) * iw;
        ov.w = (r3 + sv.w) * iw;
        og[i] = ov;
    }
}

// ---------------------------------------------------------------------------
// inputs: 0:x 1:core 2:out_f0 3:out_f1 4:out_f2 5:in_f0 6:in_f1 7:in_f2 8:mask
// ---------------------------------------------------------------------------
extern "C" void kernel_launch(void* const* d_in, const int* in_sizes, int n_in,
                              void* d_out, int out_size)
{
    const float* x      = (const float*)d_in[0];
    const float* core   = (const float*)d_in[1];
    const float* out_f0 = (const float*)d_in[2];
    const float* out_f1 = (const float*)d_in[3];
    const float* out_f2 = (const float*)d_in[4];
    const float* in_f0  = (const float*)d_in[5];
    const float* in_f1  = (const float*)d_in[6];
    const float* in_f2  = (const float*)d_in[7];
    float* out = (float*)d_out;

    void* flags_ptr = nullptr;
    cudaGetSymbolAddress(&flags_ptr, g_flags);
    cudaMemsetAsync(flags_ptr, 0, 2 * sizeof(int));

    k0_scan_mask<<<64, 256>>>((const unsigned char*)d_in[8]);
    fold_w4<<<64, 256>>>(core, out_f0, out_f1, in_f0, in_f1);
    k1_reduce_project<<<2 * GROUPS, 256>>>(x, in_f2);
    dim3 g2(GROUPS / 64, RRR / 64);
    k2_core_gemm<<<g2, 256>>>();
    k3_stream<<<2 * GROUPS, 256>>>(out_f2, d_in[8], out);
}

// round 10
// speedup vs baseline: 1.2292x; 1.1864x over previous
#include <cuda_runtime.h>
#include <cstdint>

#define GROUPS  2048
#define MM      64
#define CC      128
#define TOK     8192
#define RK      8
#define RRR     512
#define MASKN   524288

// Fragment-permuted operand storage:
//  A (T1, 2048x512): tile (mt,ks), stored [mt][ks][128]; element (tr,tc)
//      at lane=(tr&7)*4+(tc&3), reg=(tr>>3)+((tc>>2)<<1)
//  B (W4, 512x512):  tile (nt,ks), stored [nt][ks][64];  element (n,k)
//      at lane=(n&7)*4+(k&3),  reg=k>>2
__device__ float g_s  [(size_t)GROUPS * TOK];  // 64 MB group sums
__device__ float g_t1h[(size_t)GROUPS * RRR];  // 4 MB  T1 hi (permuted)
__device__ float g_t1l[(size_t)GROUPS * RRR];  // 4 MB  T1 lo (permuted)
__device__ float g_u2 [(size_t)GROUPS * RRR];  // 4 MB
__device__ float g_w4h[RRR * RRR];             // 1 MB  W4 hi (permuted)
__device__ float g_w4l[RRR * RRR];             // 1 MB  W4 lo (permuted)
__device__ int   g_flags[2];                   // [ge2, odd]

__device__ __forceinline__ void tf32_split(float v, float& hi, float& lo)
{
    unsigned hb, lb;
    asm("cvt.rna.tf32.f32 %0, %1;" : "=r"(hb) : "f"(v));
    hi = __uint_as_float(hb);
    float r = v - hi;
    asm("cvt.rna.tf32.f32 %0, %1;" : "=r"(lb) : "f"(r));
    lo = __uint_as_float(lb);
}

__device__ __forceinline__ size_t a_perm_idx(int gr, int c)
{
    int mt = gr >> 4, tr = gr & 15;
    int ks = c >> 3,  tc = c & 7;
    int lane = (tr & 7) * 4 + (tc & 3);
    int reg  = (tr >> 3) + ((tc >> 2) << 1);
    return (size_t)(mt * 64 + ks) * 128 + lane * 4 + reg;
}
__device__ __forceinline__ size_t b_perm_idx(int n, int k)
{
    int nt = n >> 3, gid = n & 7;
    int ks = k >> 3, kc = k & 7;
    int lane = gid * 4 + (kc & 3);
    int reg  = kc >> 2;
    return (size_t)(nt * 64 + ks) * 64 + lane * 2 + reg;
}

// ---------------------------------------------------------------------------
// Mask dtype scan
// ---------------------------------------------------------------------------
__global__ void __launch_bounds__(256) k0_scan_mask(const unsigned char* __restrict__ mask)
{
    const uint4* p = (const uint4*)mask;
    unsigned acc = 0;
    int i = blockIdx.x * 256 + threadIdx.x;
    for (; i < MASKN / 16; i += 64 * 256) {
        uint4 v = p[i];
        acc |= (v.x | v.y | v.z | v.w);
    }
    __shared__ unsigned sacc;
    if (threadIdx.x == 0) sacc = 0;
    __syncthreads();
    #pragma unroll
    for (int off = 16; off >= 1; off >>= 1)
        acc |= __shfl_xor_sync(0xffffffffu, acc, off);
    if ((threadIdx.x & 31) == 0) atomicOr(&sacc, acc);
    __syncthreads();
    if (threadIdx.x == 0) {
        unsigned a = sacc;
        if (a & 0xFEFEFEFEu) atomicOr(&g_flags[0], 1);
        if (a & 0xFFFFFF00u) atomicOr(&g_flags[1], 1);
    }
}

// ---------------------------------------------------------------------------
// Fold: W4[(o,p,C),(a,d,F)] -> hi/lo tf32, written fragment-permuted.
// ---------------------------------------------------------------------------
__global__ void __launch_bounds__(256) fold_w4(
    const float* __restrict__ core,
    const float* __restrict__ of0, const float* __restrict__ of1,
    const float* __restrict__ if0, const float* __restrict__ if1)
{
    __shared__ float bufA[4096], bufB[4096];
    __shared__ float sf[4][64];
    const int tid = threadIdx.x;
    const int C = blockIdx.x >> 3, F = blockIdx.x & 7;

    if (tid < 64)       sf[0][tid]       = of0[tid];
    else if (tid < 128) sf[1][tid - 64]  = of1[tid - 64];
    else if (tid < 192) sf[2][tid - 128] = if0[tid - 128];
    else                sf[3][tid - 192] = if1[tid - 192];

    #pragma unroll
    for (int i = tid; i < 4096; i += 256) {
        int A = i >> 9, B = (i >> 6) & 7, D = (i >> 3) & 7, E = i & 7;
        bufA[i] = core[A * 32768 + B * 4096 + C * 512 + D * 64 + E * 8 + F];
    }
    __syncthreads();
    #pragma unroll
    for (int i = tid; i < 4096; i += 256) {   // M1[A,B,D,d] = sum_E K * if1[d,E]
        int ABD = i >> 3, d = i & 7;
        float acc = 0.f;
        #pragma unroll
        for (int E = 0; E < 8; E++) acc += bufA[ABD * 8 + E] * sf[3][d * 8 + E];
        bufB[i] = acc;
    }
    __syncthreads();
    #pragma unroll
    for (int i = tid; i < 4096; i += 256) {   // M2[A,B,d,a] = sum_D M1 * if0[a,D]
        int AB = i >> 6, d = (i >> 3) & 7, a = i & 7;
        float acc = 0.f;
        #pragma unroll
        for (int D = 0; D < 8; D++) acc += bufB[(AB * 8 + D) * 8 + d] * sf[2][a * 8 + D];
        bufA[i] = acc;
    }
    __syncthreads();
    #pragma unroll
    for (int i = tid; i < 4096; i += 256) {   // M3[B,d,a,o] = sum_A M2 * of0[o,A]
        int B = i >> 9, d = (i >> 6) & 7, a = (i >> 3) & 7, o = i & 7;
        float acc = 0.f;
        #pragma unroll
        for (int A = 0; A < 8; A++)
            acc += bufA[((A * 8 + B) * 8 + d) * 8 + a] * sf[0][o * 8 + A];
        bufB[i] = acc;
    }
    __syncthreads();
    #pragma unroll
    for (int i = tid; i < 4096; i += 256) {   // W4 = sum_B M3 * of1[p,B]
        int o = i >> 9, p = (i >> 6) & 7, a = (i >> 3) & 7, d = i & 7;
        float acc = 0.f;
        #pragma unroll
        for (int B = 0; B < 8; B++)
            acc += bufB[((B * 8 + d) * 8 + a) * 8 + o] * sf[1][p * 8 + B];
        float hi, lo;
        tf32_split(acc, hi, lo);
        int n = (o * 8 + p) * 8 + C;
        int k = a * 64 + d * 8 + F;
        size_t idx = b_perm_idx(n, k);
        g_w4h[idx] = hi;
        g_w4l[idx] = lo;
    }
}

// ---------------------------------------------------------------------------
// Kernel 1: grid 4096 (half-group per block): s -> scratch, T1 hi/lo permuted.
// Pitch-132 smem tile -> vectorized phase 2 (LDS.128, conflict-free).
// ---------------------------------------------------------------------------
__global__ void __launch_bounds__(256) k1_reduce_project(
    const float* __restrict__ x,
    const float* __restrict__ in_f2)   // (128,8)
{
    __shared__ __align__(16) float s[32 * 132];
    __shared__ __align__(16) float f2q[8 * 132];   // [F][e]

    const int tid = threadIdx.x;
    const int g = blockIdx.x >> 1, h = blockIdx.x & 1;
    const size_t base = (size_t)g * (4 * TOK) + h * 4096;

    #pragma unroll
    for (int i = tid; i < CC * RK; i += 256) {
        int e = i >> 3, F = i & 7;
        f2q[F * 132 + e] = in_f2[i];
    }

    const float4* xb = (const float4*)(x + base);
    float4*       sg = (float4*)(g_s + (size_t)g * TOK + h * 4096);
    #pragma unroll
    for (int it = 0; it < 4; it++) {
        int i = tid + it * 256;
        float4 v0 = __ldcs(&xb[i]);
        float4 v1 = __ldcs(&xb[i + 2048]);
        float4 v2 = __ldcs(&xb[i + 4096]);
        float4 v3 = __ldcs(&xb[i + 6144]);
        float4 r;
        r.x = (v0.x + v1.x) + (v2.x + v3.x);
        r.y = (v0.y + v1.y) + (v2.y + v3.y);
        r.z = (v0.z + v1.z) + (v2.z + v3.z);
        r.w = (v0.w + v1.w) + (v2.w + v3.w);
        sg[i] = r;
        int m = i >> 5;
        int e = (i & 31) << 2;
        *(float4*)&s[m * 132 + e] = r;
    }
    __syncthreads();
    {
        int m = tid & 31;
        int F = tid >> 5;
        const float4* s4 = (const float4*)&s[m * 132];
        const float4* f4 = (const float4*)&f2q[F * 132];
        float acc = 0.f;
        #pragma unroll
        for (int e4 = 0; e4 < 32; e4++) {
            float4 a = s4[e4];
            float4 b = f4[e4];
            acc += a.x * b.x + a.y * b.y + a.z * b.z + a.w * b.w;
        }
        float hi, lo;
        tf32_split(acc, hi, lo);
        size_t idx = a_perm_idx(g, (h * 32 + m) * 8 + F);
        g_t1h[idx] = hi;
        g_t1l[idx] = lo;
    }
}

// ---------------------------------------------------------------------------
// Kernel 2: U2 = T1 @ W4^T — cp.async 4-stage pipeline (identity copy, since
// gmem is already fragment-permuted). BM=64 BN=64, 3xTF32, grid (32,8).
// ---------------------------------------------------------------------------
__device__ __forceinline__ void k2_issue(float* sA, float* sB, int ks,
                                         int bm, int bn, int tid)
{
    int half = tid >> 7, r = tid & 127;
    {   // A: 4 m-tiles x 128 floats x {hi,lo}
        int mt = r >> 5, off = (r & 31) * 4;
        const float* src = (half ? g_t1l : g_t1h)
                         + ((size_t)((bm >> 4) + mt) * 64 + ks) * 128 + off;
        unsigned dst = (unsigned)__cvta_generic_to_shared(&sA[half * 512 + mt * 128 + off]);
        asm volatile("cp.async.cg.shared.global [%0], [%1], 16;" :: "r"(dst), "l"(src));
    }
    {   // B: 8 n-tiles x 64 floats x {hi,lo}
        int nt = r >> 4, off = (r & 15) * 4;
        const float* src = (half ? g_w4l : g_w4h)
                         + ((size_t)((bn >> 3) + nt) * 64 + ks) * 64 + off;
        unsigned dst = (unsigned)__cvta_generic_to_shared(&sB[half * 512 + nt * 64 + off]);
        asm volatile("cp.async.cg.shared.global [%0], [%1], 16;" :: "r"(dst), "l"(src));
    }
}

__global__ void __launch_bounds__(256) k2_core_gemm()
{
    __shared__ __align__(16) float sA[4][1024];   // [stage][half*512 + mt*128 + c]
    __shared__ __align__(16) float sB[4][1024];   // [stage][half*512 + nt*64 + c]

    const int tid  = threadIdx.x;
    const int lane = tid & 31;
    const int wid  = tid >> 5;
    const int wm   = wid >> 2;          // 0..1
    const int wn   = wid & 3;           // 0..3
    const int gid  = lane >> 2;
    const int tig  = lane & 3;
    const int bm   = blockIdx.x * 64;
    const int bn   = blockIdx.y * 64;

    float acc[2][2][4];
    #pragma unroll
    for (int mi = 0; mi < 2; mi++)
        #pragma unroll
        for (int ni = 0; ni < 2; ni++)
            #pragma unroll
            for (int r = 0; r < 4; r++) acc[mi][ni][r] = 0.f;

    // prologue: stages 0..2 in flight
    #pragma unroll
    for (int st = 0; st < 3; st++) {
        k2_issue(sA[st], sB[st], st, bm, bn, tid);
        asm volatile("cp.async.commit_group;" ::: "memory");
    }

    for (int ks = 0; ks < 64; ks++) {
        asm volatile("cp.async.wait_group 2;" ::: "memory");
        __syncthreads();
        int st = ks & 3;
        uint4 ah[2], al[2];
        uint2 bh[2], bl[2];
        #pragma unroll
        for (int mi = 0; mi < 2; mi++) {
            ah[mi] = *(const uint4*)&sA[st][(wm * 2 + mi) * 128 + lane * 4];
            al[mi] = *(const uint4*)&sA[st][512 + (wm * 2 + mi) * 128 + lane * 4];
        }
        #pragma unroll
        for (int ni = 0; ni < 2; ni++) {
            bh[ni] = *(const uint2*)&sB[st][(wn * 2 + ni) * 64 + lane * 2];
            bl[ni] = *(const uint2*)&sB[st][512 + (wn * 2 + ni) * 64 + lane * 2];
        }
        #pragma unroll
        for (int mi = 0; mi < 2; mi++)
            #pragma unroll
            for (int ni = 0; ni < 2; ni++) {
                float* c = acc[mi][ni];
                asm volatile(
                    "mma.sync.aligned.m16n8k8.row.col.f32.tf32.tf32.f32 "
                    "{%0,%1,%2,%3}, {%4,%5,%6,%7}, {%8,%9}, {%0,%1,%2,%3};"
                    : "+f"(c[0]), "+f"(c[1]), "+f"(c[2]), "+f"(c[3])
                    : "r"(ah[mi].x), "r"(ah[mi].y), "r"(ah[mi].z), "r"(ah[mi].w),
                      "r"(bh[ni].x), "r"(bh[ni].y));
                asm volatile(
                    "mma.sync.aligned.m16n8k8.row.col.f32.tf32.tf32.f32 "
                    "{%0,%1,%2,%3}, {%4,%5,%6,%7}, {%8,%9}, {%0,%1,%2,%3};"
                    : "+f"(c[0]), "+f"(c[1]), "+f"(c[2]), "+f"(c[3])
                    : "r"(al[mi].x), "r"(al[mi].y), "r"(al[mi].z), "r"(al[mi].w),
                      "r"(bh[ni].x), "r"(bh[ni].y));
                asm volatile(
                    "mma.sync.aligned.m16n8k8.row.col.f32.tf32.tf32.f32 "
                    "{%0,%1,%2,%3}, {%4,%5,%6,%7}, {%8,%9}, {%0,%1,%2,%3};"
                    : "+f"(c[0]), "+f"(c[1]), "+f"(c[2]), "+f"(c[3])
                    : "r"(ah[mi].x), "r"(ah[mi].y), "r"(ah[mi].z), "r"(ah[mi].w),
                      "r"(bl[ni].x), "r"(bl[ni].y));
            }
        __syncthreads();   // WAR: stage st gets overwritten 3 iters from now
        if (ks < 61)
            k2_issue(sA[(ks + 3) & 3], sB[(ks + 3) & 3], ks + 3, bm, bn, tid);
        asm volatile("cp.async.commit_group;" ::: "memory");
    }

    #pragma unroll
    for (int mi = 0; mi < 2; mi++)
        #pragma unroll
        for (int ni = 0; ni < 2; ni++) {
            int row0 = bm + wm * 32 + mi * 16 + gid;
            int col  = bn + wn * 16 + ni * 8 + tig * 2;
            float* c = acc[mi][ni];
            *(float2*)&g_u2[(size_t)row0 * RRR + col]       = make_float2(c[0], c[1]);
            *(float2*)&g_u2[(size_t)(row0 + 8) * RRR + col] = make_float2(c[2], c[3]);
        }
}

// ---------------------------------------------------------------------------
// Kernel 3: grid 4096. out = (u2·f2^T + s) * invw.  f2 hoisted to registers.
// ---------------------------------------------------------------------------
__global__ void __launch_bounds__(256) k3_stream(
    const float* __restrict__ out_f2,
    const void*  __restrict__ maskp,
    float* __restrict__ out)
{
    __shared__ float f2t[RK * CC];
    __shared__ float u2s[256];
    __shared__ float invw[32];

    const int tid = threadIdx.x;
    const int g = blockIdx.x >> 1, h = blockIdx.x & 1;

    if (tid < 64)
        ((float4*)u2s)[tid] = ((const float4*)(g_u2 + (size_t)g * RRR + h * 256))[tid];
    #pragma unroll
    for (int i = tid; i < RK * CC; i += 256) {
        int q = i >> 3, Cr = i & 7;
        f2t[Cr * CC + q] = out_f2[i];
    }
    if (tid < 32) {
        int ge2 = g_flags[0], odd = g_flags[1];
        int m = h * 32 + tid;
        int w;
        if (ge2) {
            const float* mf = (const float*)maskp + (size_t)g * 256;
            w = (mf[m] != 0.f ? 0 : 1) + (mf[m + 64] != 0.f ? 0 : 1)
              + (mf[m + 128] != 0.f ? 0 : 1) + (mf[m + 192] != 0.f ? 0 : 1);
        } else if (odd) {
            const unsigned char* mb = (const unsigned char*)maskp + (size_t)g * 256;
            w = (mb[m] ? 0 : 1) + (mb[m + 64] ? 0 : 1)
              + (mb[m + 128] ? 0 : 1) + (mb[m + 192] ? 0 : 1);
        } else {
            const int* mi = (const int*)maskp + (size_t)g * 256;
            w = (mi[m] ? 0 : 1) + (mi[m + 64] ? 0 : 1)
              + (mi[m + 128] ? 0 : 1) + (mi[m + 192] ? 0 : 1);
        }
        invw[tid] = (w > 0) ? 1.0f / ((float)w + 1e-10f) : 0.0f;
    }
    __syncthreads();

    // hoist f2 columns: q0 = (tid&31)*4 is iteration-invariant
    const int q0 = (tid & 31) << 2;
    float4 rf2[8];
    #pragma unroll
    for (int Cr = 0; Cr < 8; Cr++)
        rf2[Cr] = *(const float4*)&f2t[Cr * CC + q0];

    const float4* sg = (const float4*)(g_s + (size_t)g * TOK + h * 4096);
    float4*       og = (float4*)(out + (size_t)g * TOK + h * 4096);
    #pragma unroll
    for (int it = 0; it < 4; it++) {
        int i  = tid + it * 256;
        int m  = i >> 5;
        float4 sv = __ldcs(&sg[i]);
        float r0 = 0.f, r1 = 0.f, r2 = 0.f, r3 = 0.f;
        #pragma unroll
        for (int Cr = 0; Cr < 8; Cr++) {
            float u = u2s[m * 8 + Cr];          // warp-uniform broadcast
            float4 f = rf2[Cr];
            r0 += u * f.x; r1 += u * f.y; r2 += u * f.z; r3 += u * f.w;
        }
        float iw = invw[m];
        float4 ov;
        ov.x = (r0 + sv.x) * iw;
        ov.y = (r1 + sv.y) * iw;
        ov.z = (r2 + sv.z) * iw;
        ov.w = (r3 + sv.w) * iw;
        __stcs(&og[i], ov);
    }
}

// ---------------------------------------------------------------------------
// inputs: 0:x 1:core 2:out_f0 3:out_f1 4:out_f2 5:in_f0 6:in_f1 7:in_f2 8:mask
// ---------------------------------------------------------------------------
extern "C" void kernel_launch(void* const* d_in, const int* in_sizes, int n_in,
                              void* d_out, int out_size)
{
    const float* x      = (const float*)d_in[0];
    const float* core   = (const float*)d_in[1];
    const float* out_f0 = (const float*)d_in[2];
    const float* out_f1 = (const float*)d_in[3];
    const float* out_f2 = (const float*)d_in[4];
    const float* in_f0  = (const float*)d_in[5];
    const float* in_f1  = (const float*)d_in[6];
    const float* in_f2  = (const float*)d_in[7];
    float* out = (float*)d_out;

    void* flags_ptr = nullptr;
    cudaGetSymbolAddress(&flags_ptr, g_flags);
    cudaMemsetAsync(flags_ptr, 0, 2 * sizeof(int));

    k0_scan_mask<<<64, 256>>>((const unsigned char*)d_in[8]);
    fold_w4<<<64, 256>>>(core, out_f0, out_f1, in_f0, in_f1);
    k1_reduce_project<<<2 * GROUPS, 256>>>(x, in_f2);
    dim3 g2(GROUPS / 64, RRR / 64);
    k2_core_gemm<<<g2, 256>>>();
    k3_stream<<<2 * GROUPS, 256>>>(out_f2, d_in[8], out);
}

// round 11
// speedup vs baseline: 1.2452x; 1.0130x over previous
#include <cuda_runtime.h>
#include <cstdint>

#define GROUPS  2048
#define MM      64
#define CC      128
#define TOK     8192
#define RK      8
#define RRR     512
#define MASKN   524288

// Fragment-permuted operand storage:
//  A (T1, 2048x512): tile (mt,ks), stored [mt][ks][128]; element (tr,tc)
//      at lane=(tr&7)*4+(tc&3), reg=(tr>>3)+((tc>>2)<<1)
//  B (W4, 512x512):  tile (nt,ks), stored [nt][ks][64];  element (n,k)
//      at lane=(n&7)*4+(k&3),  reg=k>>2
__device__ float g_s  [(size_t)GROUPS * TOK];  // 64 MB group sums
__device__ float g_t1h[(size_t)GROUPS * RRR];  // 4 MB  T1 hi (permuted)
__device__ float g_t1l[(size_t)GROUPS * RRR];  // 4 MB  T1 lo (permuted)
__device__ float g_u2 [(size_t)GROUPS * RRR];  // 4 MB
__device__ float g_w4h[RRR * RRR];             // 1 MB  W4 hi (permuted)
__device__ float g_w4l[RRR * RRR];             // 1 MB  W4 lo (permuted)
__device__ int   g_flags[2];                   // [ge2, odd]

__device__ __forceinline__ void tf32_split(float v, float& hi, float& lo)
{
    unsigned hb, lb;
    asm("cvt.rna.tf32.f32 %0, %1;" : "=r"(hb) : "f"(v));
    hi = __uint_as_float(hb);
    float r = v - hi;
    asm("cvt.rna.tf32.f32 %0, %1;" : "=r"(lb) : "f"(r));
    lo = __uint_as_float(lb);
}

__device__ __forceinline__ size_t a_perm_idx(int gr, int c)
{
    int mt = gr >> 4, tr = gr & 15;
    int ks = c >> 3,  tc = c & 7;
    int lane = (tr & 7) * 4 + (tc & 3);
    int reg  = (tr >> 3) + ((tc >> 2) << 1);
    return (size_t)(mt * 64 + ks) * 128 + lane * 4 + reg;
}
__device__ __forceinline__ size_t b_perm_idx(int n, int k)
{
    int nt = n >> 3, gid = n & 7;
    int ks = k >> 3, kc = k & 7;
    int lane = gid * 4 + (kc & 3);
    int reg  = kc >> 2;
    return (size_t)(nt * 64 + ks) * 64 + lane * 2 + reg;
}

// ---------------------------------------------------------------------------
// Mask dtype scan
// ---------------------------------------------------------------------------
__global__ void __launch_bounds__(256) k0_scan_mask(const unsigned char* __restrict__ mask)
{
    const uint4* p = (const uint4*)mask;
    unsigned acc = 0;
    int i = blockIdx.x * 256 + threadIdx.x;
    for (; i < MASKN / 16; i += 64 * 256) {
        uint4 v = p[i];
        acc |= (v.x | v.y | v.z | v.w);
    }
    __shared__ unsigned sacc;
    if (threadIdx.x == 0) sacc = 0;
    __syncthreads();
    #pragma unroll
    for (int off = 16; off >= 1; off >>= 1)
        acc |= __shfl_xor_sync(0xffffffffu, acc, off);
    if ((threadIdx.x & 31) == 0) atomicOr(&sacc, acc);
    __syncthreads();
    if (threadIdx.x == 0) {
        unsigned a = sacc;
        if (a & 0xFEFEFEFEu) atomicOr(&g_flags[0], 1);
        if (a & 0xFFFFFF00u) atomicOr(&g_flags[1], 1);
    }
}

// ---------------------------------------------------------------------------
// Fold: W4[(o,p,C),(a,d,F)] -> hi/lo tf32, written fragment-permuted.
// ---------------------------------------------------------------------------
__global__ void __launch_bounds__(256) fold_w4(
    const float* __restrict__ core,
    const float* __restrict__ of0, const float* __restrict__ of1,
    const float* __restrict__ if0, const float* __restrict__ if1)
{
    __shared__ float bufA[4096], bufB[4096];
    __shared__ float sf[4][64];
    const int tid = threadIdx.x;
    const int C = blockIdx.x >> 3, F = blockIdx.x & 7;

    if (tid < 64)       sf[0][tid]       = of0[tid];
    else if (tid < 128) sf[1][tid - 64]  = of1[tid - 64];
    else if (tid < 192) sf[2][tid - 128] = if0[tid - 128];
    else                sf[3][tid - 192] = if1[tid - 192];

    #pragma unroll
    for (int i = tid; i < 4096; i += 256) {
        int A = i >> 9, B = (i >> 6) & 7, D = (i >> 3) & 7, E = i & 7;
        bufA[i] = core[A * 32768 + B * 4096 + C * 512 + D * 64 + E * 8 + F];
    }
    __syncthreads();
    #pragma unroll
    for (int i = tid; i < 4096; i += 256) {   // M1[A,B,D,d] = sum_E K * if1[d,E]
        int ABD = i >> 3, d = i & 7;
        float acc = 0.f;
        #pragma unroll
        for (int E = 0; E < 8; E++) acc += bufA[ABD * 8 + E] * sf[3][d * 8 + E];
        bufB[i] = acc;
    }
    __syncthreads();
    #pragma unroll
    for (int i = tid; i < 4096; i += 256) {   // M2[A,B,d,a] = sum_D M1 * if0[a,D]
        int AB = i >> 6, d = (i >> 3) & 7, a = i & 7;
        float acc = 0.f;
        #pragma unroll
        for (int D = 0; D < 8; D++) acc += bufB[(AB * 8 + D) * 8 + d] * sf[2][a * 8 + D];
        bufA[i] = acc;
    }
    __syncthreads();
    #pragma unroll
    for (int i = tid; i < 4096; i += 256) {   // M3[B,d,a,o] = sum_A M2 * of0[o,A]
        int B = i >> 9, d = (i >> 6) & 7, a = (i >> 3) & 7, o = i & 7;
        float acc = 0.f;
        #pragma unroll
        for (int A = 0; A < 8; A++)
            acc += bufA[((A * 8 + B) * 8 + d) * 8 + a] * sf[0][o * 8 + A];
        bufB[i] = acc;
    }
    __syncthreads();
    #pragma unroll
    for (int i = tid; i < 4096; i += 256) {   // W4 = sum_B M3 * of1[p,B]
        int o = i >> 9, p = (i >> 6) & 7, a = (i >> 3) & 7, d = i & 7;
        float acc = 0.f;
        #pragma unroll
        for (int B = 0; B < 8; B++)
            acc += bufB[((B * 8 + d) * 8 + a) * 8 + o] * sf[1][p * 8 + B];
        float hi, lo;
        tf32_split(acc, hi, lo);
        int n = (o * 8 + p) * 8 + C;
        int k = a * 64 + d * 8 + F;
        size_t idx = b_perm_idx(n, k);
        g_w4h[idx] = hi;
        g_w4l[idx] = lo;
    }
}

// ---------------------------------------------------------------------------
// Kernel 1: grid 4096 (half-group per block): s -> scratch, T1 hi/lo permuted.
// ---------------------------------------------------------------------------
__global__ void __launch_bounds__(256) k1_reduce_project(
    const float* __restrict__ x,
    const float* __restrict__ in_f2)   // (128,8)
{
    __shared__ __align__(16) float s[32 * 132];
    __shared__ __align__(16) float f2q[8 * 132];   // [F][e]

    const int tid = threadIdx.x;
    const int g = blockIdx.x >> 1, h = blockIdx.x & 1;
    const size_t base = (size_t)g * (4 * TOK) + h * 4096;

    #pragma unroll
    for (int i = tid; i < CC * RK; i += 256) {
        int e = i >> 3, F = i & 7;
        f2q[F * 132 + e] = in_f2[i];
    }

    const float4* xb = (const float4*)(x + base);
    float4*       sg = (float4*)(g_s + (size_t)g * TOK + h * 4096);
    #pragma unroll
    for (int it = 0; it < 4; it++) {
        int i = tid + it * 256;
        float4 v0 = __ldcs(&xb[i]);
        float4 v1 = __ldcs(&xb[i + 2048]);
        float4 v2 = __ldcs(&xb[i + 4096]);
        float4 v3 = __ldcs(&xb[i + 6144]);
        float4 r;
        r.x = (v0.x + v1.x) + (v2.x + v3.x);
        r.y = (v0.y + v1.y) + (v2.y + v3.y);
        r.z = (v0.z + v1.z) + (v2.z + v3.z);
        r.w = (v0.w + v1.w) + (v2.w + v3.w);
        sg[i] = r;
        int m = i >> 5;
        int e = (i & 31) << 2;
        *(float4*)&s[m * 132 + e] = r;
    }
    __syncthreads();
    {
        int m = tid & 31;
        int F = tid >> 5;
        const float4* s4 = (const float4*)&s[m * 132];
        const float4* f4 = (const float4*)&f2q[F * 132];
        float acc = 0.f;
        #pragma unroll
        for (int e4 = 0; e4 < 32; e4++) {
            float4 a = s4[e4];
            float4 b = f4[e4];
            acc += a.x * b.x + a.y * b.y + a.z * b.z + a.w * b.w;
        }
        float hi, lo;
        tf32_split(acc, hi, lo);
        size_t idx = a_perm_idx(g, (h * 32 + m) * 8 + F);
        g_t1h[idx] = hi;
        g_t1l[idx] = lo;
    }
}

// ---------------------------------------------------------------------------
// Kernel 2: U2 = T1 @ W4^T — cp.async 3-stage pipeline, BK=64 (2 k8-slabs per
// stage), ONE __syncthreads per iteration. BM=64 BN=64, 3xTF32, grid (32,8).
// Static smem = 3*(8KB+8KB) = 48 KB exactly.
// ---------------------------------------------------------------------------
__device__ __forceinline__ void k2_issue_slab(float* sA, float* sB, int ks,
                                              int bm, int bn, int tid)
{
    int half = tid >> 7, r = tid & 127;
    {   // A: 4 m-tiles x 128 floats x {hi,lo}
        int mt = r >> 5, off = (r & 31) * 4;
        const float* src = (half ? g_t1l : g_t1h)
                         + ((size_t)((bm >> 4) + mt) * 64 + ks) * 128 + off;
        unsigned dst = (unsigned)__cvta_generic_to_shared(&sA[half * 512 + mt * 128 + off]);
        asm volatile("cp.async.cg.shared.global [%0], [%1], 16;" :: "r"(dst), "l"(src));
    }
    {   // B: 8 n-tiles x 64 floats x {hi,lo}
        int nt = r >> 4, off = (r & 15) * 4;
        const float* src = (half ? g_w4l : g_w4h)
                         + ((size_t)((bn >> 3) + nt) * 64 + ks) * 64 + off;
        unsigned dst = (unsigned)__cvta_generic_to_shared(&sB[half * 512 + nt * 64 + off]);
        asm volatile("cp.async.cg.shared.global [%0], [%1], 16;" :: "r"(dst), "l"(src));
    }
}

__global__ void __launch_bounds__(256) k2_core_gemm()
{
    __shared__ __align__(16) float sA[3][2048];   // [stage][slab*1024 + half*512 + mt*128 + c]
    __shared__ __align__(16) float sB[3][2048];   // [stage][slab*1024 + half*512 + nt*64  + c]

    const int tid  = threadIdx.x;
    const int lane = tid & 31;
    const int wid  = tid >> 5;
    const int wm   = wid >> 2;          // 0..1
    const int wn   = wid & 3;           // 0..3
    const int gid  = lane >> 2;
    const int tig  = lane & 3;
    const int bm   = blockIdx.x * 64;
    const int bn   = blockIdx.y * 64;

    float acc[2][2][4];
    #pragma unroll
    for (int mi = 0; mi < 2; mi++)
        #pragma unroll
        for (int ni = 0; ni < 2; ni++)
            #pragma unroll
            for (int r = 0; r < 4; r++) acc[mi][ni][r] = 0.f;

    // prologue: stages 0,1 (k-slabs {0,1} and {2,3})
    #pragma unroll
    for (int st = 0; st < 2; st++) {
        k2_issue_slab(&sA[st][0],    &sB[st][0],    st * 2,     bm, bn, tid);
        k2_issue_slab(&sA[st][1024], &sB[st][1024], st * 2 + 1, bm, bn, tid);
        asm volatile("cp.async.commit_group;" ::: "memory");
    }

    int st = 0;
    for (int it = 0; it < 32; it++) {
        asm volatile("cp.async.wait_group 1;" ::: "memory");
        __syncthreads();
        #pragma unroll
        for (int s = 0; s < 2; s++) {
            uint4 ah[2], al[2];
            uint2 bh[2], bl[2];
            #pragma unroll
            for (int mi = 0; mi < 2; mi++) {
                ah[mi] = *(const uint4*)&sA[st][s * 1024 + (wm * 2 + mi) * 128 + lane * 4];
                al[mi] = *(const uint4*)&sA[st][s * 1024 + 512 + (wm * 2 + mi) * 128 + lane * 4];
            }
            #pragma unroll
            for (int ni = 0; ni < 2; ni++) {
                bh[ni] = *(const uint2*)&sB[st][s * 1024 + (wn * 2 + ni) * 64 + lane * 2];
                bl[ni] = *(const uint2*)&sB[st][s * 1024 + 512 + (wn * 2 + ni) * 64 + lane * 2];
            }
            if (s == 0) {
                // issue next stage (overlaps the MMAs below); stage written is
                // (st+2)%3 == (it-1)%3, whose readers all passed this iter's sync
                if (it < 30) {
                    int nst = st + 2; if (nst >= 3) nst -= 3;
                    k2_issue_slab(&sA[nst][0],    &sB[nst][0],    (it + 2) * 2,     bm, bn, tid);
                    k2_issue_slab(&sA[nst][1024], &sB[nst][1024], (it + 2) * 2 + 1, bm, bn, tid);
                }
                asm volatile("cp.async.commit_group;" ::: "memory");
            }
            #pragma unroll
            for (int mi = 0; mi < 2; mi++)
                #pragma unroll
                for (int ni = 0; ni < 2; ni++) {
                    float* c = acc[mi][ni];
                    asm volatile(
                        "mma.sync.aligned.m16n8k8.row.col.f32.tf32.tf32.f32 "
                        "{%0,%1,%2,%3}, {%4,%5,%6,%7}, {%8,%9}, {%0,%1,%2,%3};"
                        : "+f"(c[0]), "+f"(c[1]), "+f"(c[2]), "+f"(c[3])
                        : "r"(ah[mi].x), "r"(ah[mi].y), "r"(ah[mi].z), "r"(ah[mi].w),
                          "r"(bh[ni].x), "r"(bh[ni].y));
                    asm volatile(
                        "mma.sync.aligned.m16n8k8.row.col.f32.tf32.tf32.f32 "
                        "{%0,%1,%2,%3}, {%4,%5,%6,%7}, {%8,%9}, {%0,%1,%2,%3};"
                        : "+f"(c[0]), "+f"(c[1]), "+f"(c[2]), "+f"(c[3])
                        : "r"(al[mi].x), "r"(al[mi].y), "r"(al[mi].z), "r"(al[mi].w),
                          "r"(bh[ni].x), "r"(bh[ni].y));
                    asm volatile(
                        "mma.sync.aligned.m16n8k8.row.col.f32.tf32.tf32.f32 "
                        "{%0,%1,%2,%3}, {%4,%5,%6,%7}, {%8,%9}, {%0,%1,%2,%3};"
                        : "+f"(c[0]), "+f"(c[1]), "+f"(c[2]), "+f"(c[3])
                        : "r"(ah[mi].x), "r"(ah[mi].y), "r"(ah[mi].z), "r"(ah[mi].w),
                          "r"(bl[ni].x), "r"(bl[ni].y));
                }
        }
        if (++st == 3) st = 0;
    }

    #pragma unroll
    for (int mi = 0; mi < 2; mi++)
        #pragma unroll
        for (int ni = 0; ni < 2; ni++) {
            int row0 = bm + wm * 32 + mi * 16 + gid;
            int col  = bn + wn * 16 + ni * 8 + tig * 2;
            float* c = acc[mi][ni];
            *(float2*)&g_u2[(size_t)row0 * RRR + col]       = make_float2(c[0], c[1]);
            *(float2*)&g_u2[(size_t)(row0 + 8) * RRR + col] = make_float2(c[2], c[3]);
        }
}

// ---------------------------------------------------------------------------
// Kernel 3: grid 4096. out = (u2·f2^T + s) * invw.  f2 hoisted to registers.
// ---------------------------------------------------------------------------
__global__ void __launch_bounds__(256) k3_stream(
    const float* __restrict__ out_f2,
    const void*  __restrict__ maskp,
    float* __restrict__ out)
{
    __shared__ float f2t[RK * CC];
    __shared__ float u2s[256];
    __shared__ float invw[32];

    const int tid = threadIdx.x;
    const int g = blockIdx.x >> 1, h = blockIdx.x & 1;

    if (tid < 64)
        ((float4*)u2s)[tid] = ((const float4*)(g_u2 + (size_t)g * RRR + h * 256))[tid];
    #pragma unroll
    for (int i = tid; i < RK * CC; i += 256) {
        int q = i >> 3, Cr = i & 7;
        f2t[Cr * CC + q] = out_f2[i];
    }
    if (tid < 32) {
        int ge2 = g_flags[0], odd = g_flags[1];
        int m = h * 32 + tid;
        int w;
        if (ge2) {
            const float* mf = (const float*)maskp + (size_t)g * 256;
            w = (mf[m] != 0.f ? 0 : 1) + (mf[m + 64] != 0.f ? 0 : 1)
              + (mf[m + 128] != 0.f ? 0 : 1) + (mf[m + 192] != 0.f ? 0 : 1);
        } else if (odd) {
            const unsigned char* mb = (const unsigned char*)maskp + (size_t)g * 256;
            w = (mb[m] ? 0 : 1) + (mb[m + 64] ? 0 : 1)
              + (mb[m + 128] ? 0 : 1) + (mb[m + 192] ? 0 : 1);
        } else {
            const int* mi = (const int*)maskp + (size_t)g * 256;
            w = (mi[m] ? 0 : 1) + (mi[m + 64] ? 0 : 1)
              + (mi[m + 128] ? 0 : 1) + (mi[m + 192] ? 0 : 1);
        }
        invw[tid] = (w > 0) ? 1.0f / ((float)w + 1e-10f) : 0.0f;
    }
    __syncthreads();

    const int q0 = (tid & 31) << 2;
    float4 rf2[8];
    #pragma unroll
    for (int Cr = 0; Cr < 8; Cr++)
        rf2[Cr] = *(const float4*)&f2t[Cr * CC + q0];

    const float4* sg = (const float4*)(g_s + (size_t)g * TOK + h * 4096);
    float4*       og = (float4*)(out + (size_t)g * TOK + h * 4096);
    #pragma unroll
    for (int it = 0; it < 4; it++) {
        int i  = tid + it * 256;
        int m  = i >> 5;
        float4 sv = __ldcs(&sg[i]);
        float r0 = 0.f, r1 = 0.f, r2 = 0.f, r3 = 0.f;
        #pragma unroll
        for (int Cr = 0; Cr < 8; Cr++) {
            float u = u2s[m * 8 + Cr];          // warp-uniform broadcast
            float4 f = rf2[Cr];
            r0 += u * f.x; r1 += u * f.y; r2 += u * f.z; r3 += u * f.w;
        }
        float iw = invw[m];
        float4 ov;
        ov.x = (r0 + sv.x) * iw;
        ov.y = (r1 + sv.y) * iw;
        ov.z = (r2 + sv.z) * iw;
        ov.w = (r3 + sv.w) * iw;
        __stcs(&og[i], ov);
    }
}

// ---------------------------------------------------------------------------
// inputs: 0:x 1:core 2:out_f0 3:out_f1 4:out_f2 5:in_f0 6:in_f1 7:in_f2 8:mask
// ---------------------------------------------------------------------------
extern "C" void kernel_launch(void* const* d_in, const int* in_sizes, int n_in,
                              void* d_out, int out_size)
{
    const float* x      = (const float*)d_in[0];
    const float* core   = (const float*)d_in[1];
    const float* out_f0 = (const float*)d_in[2];
    const float* out_f1 = (const float*)d_in[3];
    const float* out_f2 = (const float*)d_in[4];
    const float* in_f0  = (const float*)d_in[5];
    const float* in_f1  = (const float*)d_in[6];
    const float* in_f2  = (const float*)d_in[7];
    float* out = (float*)d_out;

    void* flags_ptr = nullptr;
    cudaGetSymbolAddress(&flags_ptr, g_flags);
    cudaMemsetAsync(flags_ptr, 0, 2 * sizeof(int));

    k0_scan_mask<<<64, 256>>>((const unsigned char*)d_in[8]);
    fold_w4<<<64, 256>>>(core, out_f0, out_f1, in_f0, in_f1);
    k1_reduce_project<<<2 * GROUPS, 256>>>(x, in_f2);
    dim3 g2(GROUPS / 64, RRR / 64);
    k2_core_gemm<<<g2, 256>>>();
    k3_stream<<<2 * GROUPS, 256>>>(out_f2, d_in[8], out);
}

// round 12
// speedup vs baseline: 1.3513x; 1.0852x over previous
#include <cuda_runtime.h>
#include <cstdint>

#define GROUPS  2048
#define MM      64
#define CC      128
#define TOK     8192
#define RK      8
#define RRR     512
#define MASKN   524288

// Fragment-permuted operand storage:
//  A (T1, 2048x512): tile (mt,ks), stored [mt][ks][128]; element (tr,tc)
//      at lane=(tr&7)*4+(tc&3), reg=(tr>>3)+((tc>>2)<<1)
//  B (W4, 512x512):  tile (nt,ks), stored [nt][ks][64];  element (n,k)
//      at lane=(n&7)*4+(k&3),  reg=k>>2
__device__ float g_s  [(size_t)GROUPS * TOK];  // 64 MB group sums
__device__ float g_t1h[(size_t)GROUPS * RRR];  // 4 MB  T1 hi (permuted)
__device__ float g_t1l[(size_t)GROUPS * RRR];  // 4 MB  T1 lo (permuted)
__device__ float g_u2 [(size_t)GROUPS * RRR];  // 4 MB
__device__ float g_w4h[RRR * RRR];             // 1 MB  W4 hi (permuted)
__device__ float g_w4l[RRR * RRR];             // 1 MB  W4 lo (permuted)
__device__ int   g_flags[2];                   // [ge2, odd]

__device__ __forceinline__ void tf32_split(float v, float& hi, float& lo)
{
    unsigned hb, lb;
    asm("cvt.rna.tf32.f32 %0, %1;" : "=r"(hb) : "f"(v));
    hi = __uint_as_float(hb);
    float r = v - hi;
    asm("cvt.rna.tf32.f32 %0, %1;" : "=r"(lb) : "f"(r));
    lo = __uint_as_float(lb);
}

__device__ __forceinline__ size_t a_perm_idx(int gr, int c)
{
    int mt = gr >> 4, tr = gr & 15;
    int ks = c >> 3,  tc = c & 7;
    int lane = (tr & 7) * 4 + (tc & 3);
    int reg  = (tr >> 3) + ((tc >> 2) << 1);
    return (size_t)(mt * 64 + ks) * 128 + lane * 4 + reg;
}
__device__ __forceinline__ size_t b_perm_idx(int n, int k)
{
    int nt = n >> 3, gid = n & 7;
    int ks = k >> 3, kc = k & 7;
    int lane = gid * 4 + (kc & 3);
    int reg  = kc >> 2;
    return (size_t)(nt * 64 + ks) * 64 + lane * 2 + reg;
}

// ---------------------------------------------------------------------------
// Combined fold + mask-scan kernel. blocks 0..63: fold W4; 64..127: scan mask.
// ---------------------------------------------------------------------------
__global__ void __launch_bounds__(256) fold_and_scan(
    const float* __restrict__ core,
    const float* __restrict__ of0, const float* __restrict__ of1,
    const float* __restrict__ if0, const float* __restrict__ if1,
    const unsigned char* __restrict__ mask)
{
    const int tid = threadIdx.x;

    if (blockIdx.x >= 64) {
        // ---- mask dtype scan (64 blocks) ----
        const uint4* p = (const uint4*)mask;
        unsigned acc = 0;
        int i = (blockIdx.x - 64) * 256 + tid;
        for (; i < MASKN / 16; i += 64 * 256) {
            uint4 v = p[i];
            acc |= (v.x | v.y | v.z | v.w);
        }
        __shared__ unsigned sacc;
        if (tid == 0) sacc = 0;
        __syncthreads();
        #pragma unroll
        for (int off = 16; off >= 1; off >>= 1)
            acc |= __shfl_xor_sync(0xffffffffu, acc, off);
        if ((tid & 31) == 0) atomicOr(&sacc, acc);
        __syncthreads();
        if (tid == 0) {
            unsigned a = sacc;
            if (a & 0xFEFEFEFEu) atomicOr(&g_flags[0], 1);
            if (a & 0xFFFFFF00u) atomicOr(&g_flags[1], 1);
        }
        return;
    }

    // ---- fold (64 blocks), one (C,F) pair per block ----
    __shared__ float bufA[4096], bufB[4096];
    __shared__ float sf[4][64];
    const int C = blockIdx.x >> 3, F = blockIdx.x & 7;

    if (tid < 64)       sf[0][tid]       = of0[tid];
    else if (tid < 128) sf[1][tid - 64]  = of1[tid - 64];
    else if (tid < 192) sf[2][tid - 128] = if0[tid - 128];
    else                sf[3][tid - 192] = if1[tid - 192];

    #pragma unroll
    for (int i = tid; i < 4096; i += 256) {
        int A = i >> 9, B = (i >> 6) & 7, D = (i >> 3) & 7, E = i & 7;
        bufA[i] = core[A * 32768 + B * 4096 + C * 512 + D * 64 + E * 8 + F];
    }
    __syncthreads();
    #pragma unroll
    for (int i = tid; i < 4096; i += 256) {   // M1[A,B,D,d] = sum_E K * if1[d,E]
        int ABD = i >> 3, d = i & 7;
        float acc = 0.f;
        #pragma unroll
        for (int E = 0; E < 8; E++) acc += bufA[ABD * 8 + E] * sf[3][d * 8 + E];
        bufB[i] = acc;
    }
    __syncthreads();
    #pragma unroll
    for (int i = tid; i < 4096; i += 256) {   // M2[A,B,d,a] = sum_D M1 * if0[a,D]
        int AB = i >> 6, d = (i >> 3) & 7, a = i & 7;
        float acc = 0.f;
        #pragma unroll
        for (int D = 0; D < 8; D++) acc += bufB[(AB * 8 + D) * 8 + d] * sf[2][a * 8 + D];
        bufA[i] = acc;
    }
    __syncthreads();
    #pragma unroll
    for (int i = tid; i < 4096; i += 256) {   // M3[B,d,a,o] = sum_A M2 * of0[o,A]
        int B = i >> 9, d = (i >> 6) & 7, a = (i >> 3) & 7, o = i & 7;
        float acc = 0.f;
        #pragma unroll
        for (int A = 0; A < 8; A++)
            acc += bufA[((A * 8 + B) * 8 + d) * 8 + a] * sf[0][o * 8 + A];
        bufB[i] = acc;
    }
    __syncthreads();
    #pragma unroll
    for (int i = tid; i < 4096; i += 256) {   // W4 = sum_B M3 * of1[p,B]
        int o = i >> 9, p = (i >> 6) & 7, a = (i >> 3) & 7, d = i & 7;
        float acc = 0.f;
        #pragma unroll
        for (int B = 0; B < 8; B++)
            acc += bufB[((B * 8 + d) * 8 + a) * 8 + o] * sf[1][p * 8 + B];
        float hi, lo;
        tf32_split(acc, hi, lo);
        int n = (o * 8 + p) * 8 + C;
        int k = a * 64 + d * 8 + F;
        size_t idx = b_perm_idx(n, k);
        g_w4h[idx] = hi;
        g_w4l[idx] = lo;
    }
}

// ---------------------------------------------------------------------------
// Kernel 1: grid 4096 (half-group per block): s -> scratch, T1 hi/lo permuted.
// Phase 2: thread (m, chunk) accumulates all 8 F over its 16-e slice
// (4 row LDS.128 + warp-uniform broadcasts), then 8-way partial reduction.
// ---------------------------------------------------------------------------
__global__ void __launch_bounds__(256) k1_reduce_project(
    const float* __restrict__ x,
    const float* __restrict__ in_f2)   // (128,8)
{
    __shared__ __align__(16) float s[32 * 132];
    __shared__ __align__(16) float f2q[8 * 132];   // [F][e]
    __shared__ __align__(16) float part[32 * 68];  // p[m][c][F] = m*68+c*8+F

    const int tid = threadIdx.x;
    const int g = blockIdx.x >> 1, h = blockIdx.x & 1;
    const size_t base = (size_t)g * (4 * TOK) + h * 4096;

    #pragma unroll
    for (int i = tid; i < CC * RK; i += 256) {
        int e = i >> 3, F = i & 7;
        f2q[F * 132 + e] = in_f2[i];
    }

    const float4* xb = (const float4*)(x + base);
    float4*       sg = (float4*)(g_s + (size_t)g * TOK + h * 4096);
    #pragma unroll
    for (int it = 0; it < 4; it++) {
        int i = tid + it * 256;
        float4 v0 = __ldcs(&xb[i]);
        float4 v1 = __ldcs(&xb[i + 2048]);
        float4 v2 = __ldcs(&xb[i + 4096]);
        float4 v3 = __ldcs(&xb[i + 6144]);
        float4 r;
        r.x = (v0.x + v1.x) + (v2.x + v3.x);
        r.y = (v0.y + v1.y) + (v2.y + v3.y);
        r.z = (v0.z + v1.z) + (v2.z + v3.z);
        r.w = (v0.w + v1.w) + (v2.w + v3.w);
        sg[i] = r;
        int m = i >> 5;
        int e = (i & 31) << 2;
        *(float4*)&s[m * 132 + e] = r;
    }
    __syncthreads();

    // phase 2a: partials. m = tid&31 (lane), c = tid>>5 (warp-uniform chunk)
    {
        int m = tid & 31;
        int c = tid >> 5;
        const float4* s4 = (const float4*)&s[m * 132 + c * 16];
        float acc[8];
        #pragma unroll
        for (int F = 0; F < 8; F++) acc[F] = 0.f;
        #pragma unroll
        for (int q = 0; q < 4; q++) {
            float4 a = s4[q];                       // row read, conflict-free
            #pragma unroll
            for (int F = 0; F < 8; F++) {
                float4 b = *(const float4*)&f2q[F * 132 + c * 16 + q * 4]; // broadcast
                acc[F] += a.x * b.x + a.y * b.y + a.z * b.z + a.w * b.w;
            }
        }
        #pragma unroll
        for (int F = 0; F < 8; F += 4)
            *(float4*)&part[m * 68 + c * 8 + F] = make_float4(acc[F], acc[F+1], acc[F+2], acc[F+3]);
    }
    __syncthreads();

    // phase 2b: reduce 8 chunks -> t1[m,F], tf32-split, permuted store
    {
        int m = tid >> 3, F = tid & 7;
        float acc = 0.f;
        #pragma unroll
        for (int c = 0; c < 8; c++)
            acc += part[m * 68 + c * 8 + F];
        float hi, lo;
        tf32_split(acc, hi, lo);
        size_t idx = a_perm_idx(g, (h * 32 + m) * 8 + F);
        g_t1h[idx] = hi;
        g_t1l[idx] = lo;
    }
}

// ---------------------------------------------------------------------------
// Kernel 2: U2 = T1 @ W4^T — cp.async 3-stage pipeline, BK=64 (2 k8-slabs per
// stage), ONE __syncthreads per iteration. BM=64 BN=64, 3xTF32, grid (32,8).
// ---------------------------------------------------------------------------
__device__ __forceinline__ void k2_issue_slab(float* sA, float* sB, int ks,
                                              int bm, int bn, int tid)
{
    int half = tid >> 7, r = tid & 127;
    {   // A: 4 m-tiles x 128 floats x {hi,lo}
        int mt = r >> 5, off = (r & 31) * 4;
        const float* src = (half ? g_t1l : g_t1h)
                         + ((size_t)((bm >> 4) + mt) * 64 + ks) * 128 + off;
        unsigned dst = (unsigned)__cvta_generic_to_shared(&sA[half * 512 + mt * 128 + off]);
        asm volatile("cp.async.cg.shared.global [%0], [%1], 16;" :: "r"(dst), "l"(src));
    }
    {   // B: 8 n-tiles x 64 floats x {hi,lo}
        int nt = r >> 4, off = (r & 15) * 4;
        const float* src = (half ? g_w4l : g_w4h)
                         + ((size_t)((bn >> 3) + nt) * 64 + ks) * 64 + off;
        unsigned dst = (unsigned)__cvta_generic_to_shared(&sB[half * 512 + nt * 64 + off]);
        asm volatile("cp.async.cg.shared.global [%0], [%1], 16;" :: "r"(dst), "l"(src));
    }
}

__global__ void __launch_bounds__(256) k2_core_gemm()
{
    __shared__ __align__(16) float sA[3][2048];
    __shared__ __align__(16) float sB[3][2048];

    const int tid  = threadIdx.x;
    const int lane = tid & 31;
    const int wid  = tid >> 5;
    const int wm   = wid >> 2;          // 0..1
    const int wn   = wid & 3;           // 0..3
    const int gid  = lane >> 2;
    const int tig  = lane & 3;
    const int bm   = blockIdx.x * 64;
    const int bn   = blockIdx.y * 64;

    float acc[2][2][4];
    #pragma unroll
    for (int mi = 0; mi < 2; mi++)
        #pragma unroll
        for (int ni = 0; ni < 2; ni++)
            #pragma unroll
            for (int r = 0; r < 4; r++) acc[mi][ni][r] = 0.f;

    #pragma unroll
    for (int st = 0; st < 2; st++) {
        k2_issue_slab(&sA[st][0],    &sB[st][0],    st * 2,     bm, bn, tid);
        k2_issue_slab(&sA[st][1024], &sB[st][1024], st * 2 + 1, bm, bn, tid);
        asm volatile("cp.async.commit_group;" ::: "memory");
    }

    int st = 0;
    for (int it = 0; it < 32; it++) {
        asm volatile("cp.async.wait_group 1;" ::: "memory");
        __syncthreads();
        #pragma unroll
        for (int s = 0; s < 2; s++) {
            uint4 ah[2], al[2];
            uint2 bh[2], bl[2];
            #pragma unroll
            for (int mi = 0; mi < 2; mi++) {
                ah[mi] = *(const uint4*)&sA[st][s * 1024 + (wm * 2 + mi) * 128 + lane * 4];
                al[mi] = *(const uint4*)&sA[st][s * 1024 + 512 + (wm * 2 + mi) * 128 + lane * 4];
            }
            #pragma unroll
            for (int ni = 0; ni < 2; ni++) {
                bh[ni] = *(const uint2*)&sB[st][s * 1024 + (wn * 2 + ni) * 64 + lane * 2];
                bl[ni] = *(const uint2*)&sB[st][s * 1024 + 512 + (wn * 2 + ni) * 64 + lane * 2];
            }
            if (s == 0) {
                if (it < 30) {
                    int nst = st + 2; if (nst >= 3) nst -= 3;
                    k2_issue_slab(&sA[nst][0],    &sB[nst][0],    (it + 2) * 2,     bm, bn, tid);
                    k2_issue_slab(&sA[nst][1024], &sB[nst][1024], (it + 2) * 2 + 1, bm, bn, tid);
                }
                asm volatile("cp.async.commit_group;" ::: "memory");
            }
            #pragma unroll
            for (int mi = 0; mi < 2; mi++)
                #pragma unroll
                for (int ni = 0; ni < 2; ni++) {
                    float* c = acc[mi][ni];
                    asm volatile(
                        "mma.sync.aligned.m16n8k8.row.col.f32.tf32.tf32.f32 "
                        "{%0,%1,%2,%3}, {%4,%5,%6,%7}, {%8,%9}, {%0,%1,%2,%3};"
                        : "+f"(c[0]), "+f"(c[1]), "+f"(c[2]), "+f"(c[3])
                        : "r"(ah[mi].x), "r"(ah[mi].y), "r"(ah[mi].z), "r"(ah[mi].w),
                          "r"(bh[ni].x), "r"(bh[ni].y));
                    asm volatile(
                        "mma.sync.aligned.m16n8k8.row.col.f32.tf32.tf32.f32 "
                        "{%0,%1,%2,%3}, {%4,%5,%6,%7}, {%8,%9}, {%0,%1,%2,%3};"
                        : "+f"(c[0]), "+f"(c[1]), "+f"(c[2]), "+f"(c[3])
                        : "r"(al[mi].x), "r"(al[mi].y), "r"(al[mi].z), "r"(al[mi].w),
                          "r"(bh[ni].x), "r"(bh[ni].y));
                    asm volatile(
                        "mma.sync.aligned.m16n8k8.row.col.f32.tf32.tf32.f32 "
                        "{%0,%1,%2,%3}, {%4,%5,%6,%7}, {%8,%9}, {%0,%1,%2,%3};"
                        : "+f"(c[0]), "+f"(c[1]), "+f"(c[2]), "+f"(c[3])
                        : "r"(ah[mi].x), "r"(ah[mi].y), "r"(ah[mi].z), "r"(ah[mi].w),
                          "r"(bl[ni].x), "r"(bl[ni].y));
                }
        }
        if (++st == 3) st = 0;
    }

    #pragma unroll
    for (int mi = 0; mi < 2; mi++)
        #pragma unroll
        for (int ni = 0; ni < 2; ni++) {
            int row0 = bm + wm * 32 + mi * 16 + gid;
            int col  = bn + wn * 16 + ni * 8 + tig * 2;
            float* c = acc[mi][ni];
            *(float2*)&g_u2[(size_t)row0 * RRR + col]       = make_float2(c[0], c[1]);
            *(float2*)&g_u2[(size_t)(row0 + 8) * RRR + col] = make_float2(c[2], c[3]);
        }
}

// ---------------------------------------------------------------------------
// Kernel 3: grid 4096. out = (u2·f2^T + s) * invw.  f2 hoisted to registers.
// ---------------------------------------------------------------------------
__global__ void __launch_bounds__(256) k3_stream(
    const float* __restrict__ out_f2,
    const void*  __restrict__ maskp,
    float* __restrict__ out)
{
    __shared__ float f2t[RK * CC];
    __shared__ float u2s[256];
    __shared__ float invw[32];

    const int tid = threadIdx.x;
    const int g = blockIdx.x >> 1, h = blockIdx.x & 1;

    if (tid < 64)
        ((float4*)u2s)[tid] = ((const float4*)(g_u2 + (size_t)g * RRR + h * 256))[tid];
    #pragma unroll
    for (int i = tid; i < RK * CC; i += 256) {
        int q = i >> 3, Cr = i & 7;
        f2t[Cr * CC + q] = out_f2[i];
    }
    if (tid < 32) {
        int ge2 = g_flags[0], odd = g_flags[1];
        int m = h * 32 + tid;
        int w;
        if (ge2) {
            const float* mf = (const float*)maskp + (size_t)g * 256;
            w = (mf[m] != 0.f ? 0 : 1) + (mf[m + 64] != 0.f ? 0 : 1)
              + (mf[m + 128] != 0.f ? 0 : 1) + (mf[m + 192] != 0.f ? 0 : 1);
        } else if (odd) {
            const unsigned char* mb = (const unsigned char*)maskp + (size_t)g * 256;
            w = (mb[m] ? 0 : 1) + (mb[m + 64] ? 0 : 1)
              + (mb[m + 128] ? 0 : 1) + (mb[m + 192] ? 0 : 1);
        } else {
            const int* mi = (const int*)maskp + (size_t)g * 256;
            w = (mi[m] ? 0 : 1) + (mi[m + 64] ? 0 : 1)
              + (mi[m + 128] ? 0 : 1) + (mi[m + 192] ? 0 : 1);
        }
        invw[tid] = (w > 0) ? 1.0f / ((float)w + 1e-10f) : 0.0f;
    }
    __syncthreads();

    const int q0 = (tid & 31) << 2;
    float4 rf2[8];
    #pragma unroll
    for (int Cr = 0; Cr < 8; Cr++)
        rf2[Cr] = *(const float4*)&f2t[Cr * CC + q0];

    const float4* sg = (const float4*)(g_s + (size_t)g * TOK + h * 4096);
    float4*       og = (float4*)(out + (size_t)g * TOK + h * 4096);
    #pragma unroll
    for (int it = 0; it < 4; it++) {
        int i  = tid + it * 256;
        int m  = i >> 5;
        float4 sv = __ldcs(&sg[i]);
        float r0 = 0.f, r1 = 0.f, r2 = 0.f, r3 = 0.f;
        #pragma unroll
        for (int Cr = 0; Cr < 8; Cr++) {
            float u = u2s[m * 8 + Cr];
            float4 f = rf2[Cr];
            r0 += u * f.x; r1 += u * f.y; r2 += u * f.z; r3 += u * f.w;
        }
        float iw = invw[m];
        float4 ov;
        ov.x = (r0 + sv.x) * iw;
        ov.y = (r1 + sv.y) * iw;
        ov.z = (r2 + sv.z) * iw;
        ov.w = (r3 + sv.w) * iw;
        __stcs(&og[i], ov);
    }
}

// ---------------------------------------------------------------------------
// inputs: 0:x 1:core 2:out_f0 3:out_f1 4:out_f2 5:in_f0 6:in_f1 7:in_f2 8:mask
// ---------------------------------------------------------------------------
extern "C" void kernel_launch(void* const* d_in, const int* in_sizes, int n_in,
                              void* d_out, int out_size)
{
    const float* x      = (const float*)d_in[0];
    const float* core   = (const float*)d_in[1];
    const float* out_f0 = (const float*)d_in[2];
    const float* out_f1 = (const float*)d_in[3];
    const float* out_f2 = (const float*)d_in[4];
    const float* in_f0  = (const float*)d_in[5];
    const float* in_f1  = (const float*)d_in[6];
    const float* in_f2  = (const float*)d_in[7];
    float* out = (float*)d_out;

    void* flags_ptr = nullptr;
    cudaGetSymbolAddress(&flags_ptr, g_flags);
    cudaMemsetAsync(flags_ptr, 0, 2 * sizeof(int));

    fold_and_scan<<<128, 256>>>(core, out_f0, out_f1, in_f0, in_f1,
                                (const unsigned char*)d_in[8]);
    k1_reduce_project<<<2 * GROUPS, 256>>>(x, in_f2);
    dim3 g2(GROUPS / 64, RRR / 64);
    k2_core_gemm<<<g2, 256>>>();
    k3_stream<<<2 * GROUPS, 256>>>(out_f2, d_in[8], out);
}